// round 7
// baseline (speedup 1.0000x reference)
#include <cuda_runtime.h>
#include <cuda_bf16.h>
#include <cstdint>

#define CH    64
#define EPSV  1e-5f
#define MAXN  100000
#define MAXK  27

// ================= scratch (__device__ globals, alloc-free) =================
__device__ float g_buf1[MAXN * CH];      // conv1 raw output (fp32)
__device__ float g_buf2[MAXN * CH];      // conv2 raw output (fp32)
__device__ float g_stats[256];           // [sum1, sumsq1, sum2, sumsq2]
__device__ float g_sb[256];              // [scale1, shift1, scale2, shift2]
// fused hi/lo feature rows: row r occupies 128 bf16 = 256B: [64 hi | 64 lo]
__device__ __align__(16) __nv_bfloat16 g_f[MAXN * 128];
// W pre-packed into mma.sync B-fragment order (column-permuted): [k][2048] u32
__device__ __align__(16) uint32_t g_WfH1[MAXK * 2048];
__device__ __align__(16) uint32_t g_WfL1[MAXK * 2048];
__device__ __align__(16) uint32_t g_WfH2[MAXK * 2048];
__device__ __align__(16) uint32_t g_WfL2[MAXK * 2048];

// ================= helpers =================
__device__ __forceinline__ uint32_t smem_u32(const void* p) {
    uint32_t a;
    asm("{ .reg .u64 t; cvta.to.shared.u64 t, %1; cvt.u32.u64 %0, t; }" : "=r"(a) : "l"(p));
    return a;
}

__device__ __forceinline__ void ldmatrix_x4(uint32_t* r, uint32_t addr) {
    asm volatile("ldmatrix.sync.aligned.m8n8.x4.shared.b16 {%0,%1,%2,%3}, [%4];"
                 : "=r"(r[0]), "=r"(r[1]), "=r"(r[2]), "=r"(r[3]) : "r"(addr));
}

__device__ __forceinline__ void mma16816(float* c, const uint32_t* a,
                                         uint32_t b0, uint32_t b1) {
    asm volatile(
        "mma.sync.aligned.m16n8k16.row.col.f32.bf16.bf16.f32 "
        "{%0,%1,%2,%3}, {%4,%5,%6,%7}, {%8,%9}, {%0,%1,%2,%3};"
        : "+f"(c[0]), "+f"(c[1]), "+f"(c[2]), "+f"(c[3])
        : "r"(a[0]), "r"(a[1]), "r"(a[2]), "r"(a[3]), "r"(b0), "r"(b1));
}

// SMEM layout for conv kernel (dynamic)
#define OFF_AH   0
#define OFF_AL   16384
#define OFF_BH   32768
#define OFF_BL   40960
#define OFF_IIDX 49152
#define OFF_OIDX 49664
#define SMEM_BYTES 50176

// ================= kernels =================

__global__ void zero_kernel(int total4)
{
    const float4 z = make_float4(0.f, 0.f, 0.f, 0.f);
    int i = blockIdx.x * blockDim.x + threadIdx.x;
    for (int j = i; j < total4; j += gridDim.x * blockDim.x) {
        reinterpret_cast<float4*>(g_buf1)[j] = z;
        reinterpret_cast<float4*>(g_buf2)[j] = z;
    }
    if (blockIdx.x == 0 && threadIdx.x < 64)
        reinterpret_cast<float4*>(g_stats)[threadIdx.x] = z;
}

// W[k][cin][cout] fp32 -> bf16 hi/lo split packed in mma B-fragment order,
// with output columns PERMUTED so each lane's 4 accumulator values from an
// (even,odd) nt-tile pair hit 4 contiguous global columns (enables red.v4).
// u32 index i: reg = i&1, lane = (i>>1)&31, nt = (i>>6)&7, ks = i>>9
// k0 = ks*16 + (lane&3)*2 + reg*8 ; local col l = lane>>2
// source col n = 16*(nt>>1) + 4*(l>>1) + 2*(nt&1) + (l&1)
__global__ __launch_bounds__(256)
void prep_w_kernel(const float* __restrict__ W1, const float* __restrict__ W2, int K)
{
    const int k     = blockIdx.x;
    const int layer = blockIdx.y;
    const float* Wk = (layer ? W2 : W1) + (size_t)k * 4096;
    uint32_t* dh = (layer ? g_WfH2 : g_WfH1) + (size_t)k * 2048;
    uint32_t* dl = (layer ? g_WfL2 : g_WfL1) + (size_t)k * 2048;

    for (int i = threadIdx.x; i < 2048; i += 256) {
        const int reg  = i & 1;
        const int lane = (i >> 1) & 31;
        const int nt   = (i >> 6) & 7;
        const int ks   = i >> 9;
        const int k0   = ks * 16 + (lane & 3) * 2 + reg * 8;
        const int l    = lane >> 2;
        const int n    = 16 * (nt >> 1) + 4 * (l >> 1) + 2 * (nt & 1) + (l & 1);
        const float v0 = Wk[k0 * 64 + n];
        const float v1 = Wk[(k0 + 1) * 64 + n];
        const __nv_bfloat16 h0 = __float2bfloat16(v0);
        const __nv_bfloat16 h1 = __float2bfloat16(v1);
        const __nv_bfloat16 l0 = __float2bfloat16(v0 - __bfloat162float(h0));
        const __nv_bfloat16 l1 = __float2bfloat16(v1 - __bfloat162float(h1));
        dh[i] = (uint32_t)__bfloat16_as_ushort(h0)
              | ((uint32_t)__bfloat16_as_ushort(h1) << 16);
        dl[i] = (uint32_t)__bfloat16_as_ushort(l0)
              | ((uint32_t)__bfloat16_as_ushort(l1) << 16);
    }
}

// fp32 rows -> fused bf16 hi/lo row [64 hi | 64 lo] (optional fused relu(bn))
__global__ __launch_bounds__(256)
void prep_feat_kernel(const float* __restrict__ src, const float* __restrict__ sb,
                      int N)
{
    const int gid = blockIdx.x * blockDim.x + threadIdx.x;
    if (gid >= N * 8) return;
    const int row = gid >> 3;
    const int c0  = (gid & 7) * 8;

    const float4 v0 = reinterpret_cast<const float4*>(src + (size_t)row * 64 + c0)[0];
    const float4 v1 = reinterpret_cast<const float4*>(src + (size_t)row * 64 + c0)[1];
    float v[8] = {v0.x, v0.y, v0.z, v0.w, v1.x, v1.y, v1.z, v1.w};

    if (sb) {
        #pragma unroll
        for (int j = 0; j < 8; ++j)
            v[j] = fmaxf(fmaf(v[j], sb[c0 + j], sb[64 + c0 + j]), 0.f);
    }

    union { __nv_bfloat16 h[8]; uint4 u; } uh, ul;
    #pragma unroll
    for (int j = 0; j < 8; ++j) {
        const __nv_bfloat16 hi = __float2bfloat16(v[j]);
        uh.h[j] = hi;
        ul.h[j] = __float2bfloat16(v[j] - __bfloat162float(hi));
    }
    // fused row: 16 uint4 per row; hi at [0..7], lo at [8..15]
    reinterpret_cast<uint4*>(g_f)[(size_t)row * 16 + (c0 >> 3)]     = uh.u;
    reinterpret_cast<uint4*>(g_f)[(size_t)row * 16 + 8 + (c0 >> 3)] = ul.u;
}

// gather -> mma.sync bf16-split -> red.v4 scatter
// 8 warps arranged 4(row)x2(col); each warp: 32 rows x 32 cols.
// 4 CTAs/SM forced (regs <= 64). Gather reads fused 256B rows (one stream).
__global__ __launch_bounds__(256, 4)
void conv_mma_kernel(const __nv_bfloat16* __restrict__ f,
                     const uint32_t* __restrict__ WfH,
                     const uint32_t* __restrict__ WfL,
                     const int* __restrict__ in_maps,
                     const int* __restrict__ out_maps,
                     float* __restrict__ out,
                     int M)
{
    extern __shared__ char sm[];
    char*     Ah   = sm + OFF_AH;
    char*     Al   = sm + OFF_AL;
    uint32_t* BH   = reinterpret_cast<uint32_t*>(sm + OFF_BH);
    uint32_t* BL   = reinterpret_cast<uint32_t*>(sm + OFF_BL);
    int*      iidx = reinterpret_cast<int*>(sm + OFF_IIDX);
    int*      oidx = reinterpret_cast<int*>(sm + OFF_OIDX);

    const int t    = threadIdx.x;
    const int lane = t & 31;
    const int w    = t >> 5;
    const int wr   = w >> 1;      // row group 0..3
    const int wc   = w & 1;       // col group 0..1
    const int k    = blockIdx.y;
    const int m0   = blockIdx.x * 128;

    // maps
    if (t < 128) {
        const int m = m0 + t;
        iidx[t] = (m < M) ? in_maps [(size_t)k * M + m] : -1;
        oidx[t] = (m < M) ? out_maps[(size_t)k * M + m] : -1;
    }
    // B-fragment copy (1024 uint4 total across hi+lo)
    {
        const uint4* sh = reinterpret_cast<const uint4*>(WfH + (size_t)k * 2048);
        const uint4* sl = reinterpret_cast<const uint4*>(WfL + (size_t)k * 2048);
        reinterpret_cast<uint4*>(BH)[t]       = sh[t];
        reinterpret_cast<uint4*>(BH)[t + 256] = sh[t + 256];
        reinterpret_cast<uint4*>(BL)[t]       = sl[t];
        reinterpret_cast<uint4*>(BL)[t + 256] = sl[t + 256];
    }
    __syncthreads();

    // gather A (hi/lo): 8 lanes per row, one 16B chunk each, fused row stream.
    {
        const int c = t & 7;          // chunk 0..7
        const int g = t >> 3;         // row sub-index 0..31
        const uint4 z = make_uint4(0, 0, 0, 0);
        #pragma unroll
        for (int it = 0; it < 4; ++it) {
            const int row = it * 32 + g;
            const int src = iidx[row];
            uint4 vh = z, vl = z;
            if (src >= 0) {
                const uint4* base = reinterpret_cast<const uint4*>(f) + (size_t)src * 16;
                vh = base[c];
                vl = base[c + 8];
            }
            const int d = row * 128 + ((c ^ (row & 7)) << 4);
            *reinterpret_cast<uint4*>(Ah + d) = vh;
            *reinterpret_cast<uint4*>(Al + d) = vl;
        }
    }
    __syncthreads();

    // MMA mainloop: warp covers rows [wr*32, wr*32+32), cols [wc*32, wc*32+32)
    float acc[2][4][4];
    #pragma unroll
    for (int rt = 0; rt < 2; ++rt)
        #pragma unroll
        for (int nl = 0; nl < 4; ++nl)
            #pragma unroll
            for (int j = 0; j < 4; ++j) acc[rt][nl][j] = 0.f;

    const uint32_t ahb = smem_u32(Ah);
    const uint32_t alb = smem_u32(Al);
    const int half = lane >> 4;

    #pragma unroll
    for (int ks = 0; ks < 4; ++ks) {
        uint32_t aH[2][4], aL[2][4];
        #pragma unroll
        for (int rt = 0; rt < 2; ++rt) {
            const int row   = wr * 32 + rt * 16 + (lane & 15);
            const int chunk = ks * 2 + half;
            const uint32_t off = row * 128 + ((chunk ^ (row & 7)) << 4);
            ldmatrix_x4(aH[rt], ahb + off);
            ldmatrix_x4(aL[rt], alb + off);
        }
        #pragma unroll
        for (int nl = 0; nl < 4; ++nl) {
            const int nt = wc * 4 + nl;
            const int fi = ((ks * 8 + nt) * 32 + lane) * 2;
            const uint2 bh = *reinterpret_cast<const uint2*>(&BH[fi]);
            const uint2 bl = *reinterpret_cast<const uint2*>(&BL[fi]);
            #pragma unroll
            for (int rt = 0; rt < 2; ++rt) {
                mma16816(acc[rt][nl], aH[rt], bh.x, bh.y);
                mma16816(acc[rt][nl], aH[rt], bl.x, bl.y);
                mma16816(acc[rt][nl], aL[rt], bh.x, bh.y);
            }
        }
    }

    // scatter via red.v4: permuted cols -> pair (2p,2p+1) lands contiguously
    // global pair gp = wc*2 + p, col base 16*gp + 4*(lane&3)
    #pragma unroll
    for (int rt = 0; rt < 2; ++rt) {
        const int r0 = wr * 32 + rt * 16 + (lane >> 2);
        const int o0 = oidx[r0];
        const int o1 = oidx[r0 + 8];
        const int cb = 4 * (lane & 3);
        #pragma unroll
        for (int p = 0; p < 2; ++p) {
            const int col = 16 * (wc * 2 + p) + cb;
            if (o0 >= 0) {
                asm volatile("red.global.add.v4.f32 [%0], {%1, %2, %3, %4};"
                    :: "l"(out + (size_t)o0 * 64 + col),
                       "f"(acc[rt][2*p][0]), "f"(acc[rt][2*p][1]),
                       "f"(acc[rt][2*p+1][0]), "f"(acc[rt][2*p+1][1]) : "memory");
            }
            if (o1 >= 0) {
                asm volatile("red.global.add.v4.f32 [%0], {%1, %2, %3, %4};"
                    :: "l"(out + (size_t)o1 * 64 + col),
                       "f"(acc[rt][2*p][2]), "f"(acc[rt][2*p][3]),
                       "f"(acc[rt][2*p+1][2]), "f"(acc[rt][2*p+1][3]) : "memory");
            }
        }
    }
}

// per-channel sum / sumsq
__global__ __launch_bounds__(256)
void stats_kernel(const float* __restrict__ x, int N, float* __restrict__ sums)
{
    const int t   = threadIdx.x;
    const int col = t & 63;
    const int rg  = t >> 6;
    float s = 0.f, ss = 0.f;
    for (int r = blockIdx.x * 4 + rg; r < N; r += gridDim.x * 4) {
        const float v = x[(size_t)r * 64 + col];
        s += v; ss += v * v;
    }
    __shared__ float sh[512];
    sh[t] = s; sh[256 + t] = ss;
    __syncthreads();
    if (t < 64) {
        float S  = sh[t]       + sh[t + 64]       + sh[t + 128]       + sh[t + 192];
        float SS = sh[256 + t] + sh[256 + t + 64] + sh[256 + t + 128] + sh[256 + t + 192];
        atomicAdd(&sums[t],      S);
        atomicAdd(&sums[64 + t], SS);
    }
}

__global__ void finalize_kernel(const float* __restrict__ sums,
                                const float* __restrict__ gamma,
                                const float* __restrict__ beta,
                                float invN, float* __restrict__ sb)
{
    const int t = threadIdx.x;
    const float mean = sums[t] * invN;
    const float var  = fmaxf(sums[64 + t] * invN - mean * mean, 0.f);
    const float s    = gamma[t] * rsqrtf(var + EPSV);
    sb[t]      = s;
    sb[64 + t] = beta[t] - mean * s;
}

__global__ __launch_bounds__(256)
void final_kernel(const float* __restrict__ conv2, const float* __restrict__ sb2,
                  const float* __restrict__ feat, float* __restrict__ out, int n4)
{
    int i = blockIdx.x * blockDim.x + threadIdx.x;
    for (int j = i; j < n4; j += gridDim.x * blockDim.x) {
        const float4 v = reinterpret_cast<const float4*>(conv2)[j];
        const float4 f = reinterpret_cast<const float4*>(feat)[j];
        const int c0 = (j & 15) * 4;
        float4 r;
        r.x = fmaxf(fmaf(v.x, sb2[c0 + 0], sb2[64 + c0 + 0]) + f.x, 0.f);
        r.y = fmaxf(fmaf(v.y, sb2[c0 + 1], sb2[64 + c0 + 1]) + f.y, 0.f);
        r.z = fmaxf(fmaf(v.z, sb2[c0 + 2], sb2[64 + c0 + 2]) + f.z, 0.f);
        r.w = fmaxf(fmaf(v.w, sb2[c0 + 3], sb2[64 + c0 + 3]) + f.w, 0.f);
        reinterpret_cast<float4*>(out)[j] = r;
    }
}

// ================= launcher =================
extern "C" void kernel_launch(void* const* d_in, const int* in_sizes, int n_in,
                              void* d_out, int out_size)
{
    const float* features = (const float*)d_in[0];
    const float* W1       = (const float*)d_in[1];
    const float* gamma1   = (const float*)d_in[2];
    const float* beta1    = (const float*)d_in[3];
    const float* W2       = (const float*)d_in[4];
    const float* gamma2   = (const float*)d_in[5];
    const float* beta2    = (const float*)d_in[6];
    const int*   in_maps  = (const int*)d_in[7];
    const int*   out_maps = (const int*)d_in[8];
    float*       out      = (float*)d_out;

    const int N = in_sizes[0] / CH;
    const int K = in_sizes[1] / (CH * CH);
    const int M = in_sizes[7] / K;

    float* buf1;  cudaGetSymbolAddress((void**)&buf1,  g_buf1);
    float* buf2;  cudaGetSymbolAddress((void**)&buf2,  g_buf2);
    float* stats; cudaGetSymbolAddress((void**)&stats, g_stats);
    float* sb;    cudaGetSymbolAddress((void**)&sb,    g_sb);
    __nv_bfloat16* f;
    cudaGetSymbolAddress((void**)&f, g_f);
    uint32_t *wh1, *wl1, *wh2, *wl2;
    cudaGetSymbolAddress((void**)&wh1, g_WfH1);
    cudaGetSymbolAddress((void**)&wl1, g_WfL1);
    cudaGetSymbolAddress((void**)&wh2, g_WfH2);
    cudaGetSymbolAddress((void**)&wl2, g_WfL2);

    cudaFuncSetAttribute(conv_mma_kernel,
                         cudaFuncAttributeMaxDynamicSharedMemorySize, SMEM_BYTES);

    const int total4 = N * (CH / 4);
    const float invN = 1.0f / (float)N;
    const dim3 convGrid((M + 127) / 128, K);
    const int pfBlocks = (N * 8 + 255) / 256;

    zero_kernel<<<1024, 256>>>(total4);
    prep_w_kernel<<<dim3(K, 2), 256>>>(W1, W2, K);

    // conv1
    prep_feat_kernel<<<pfBlocks, 256>>>(features, nullptr, N);
    conv_mma_kernel<<<convGrid, 256, SMEM_BYTES>>>(f, wh1, wl1,
                                                   in_maps, out_maps, buf1, M);
    stats_kernel<<<512, 256>>>(buf1, N, stats);
    finalize_kernel<<<1, 64>>>(stats, gamma1, beta1, invN, sb);

    // conv2 (BN1+ReLU fused into split pass)
    prep_feat_kernel<<<pfBlocks, 256>>>(buf1, sb, N);
    conv_mma_kernel<<<convGrid, 256, SMEM_BYTES>>>(f, wh2, wl2,
                                                   in_maps, out_maps, buf2, M);
    stats_kernel<<<512, 256>>>(buf2, N, stats + 128);
    finalize_kernel<<<1, 64>>>(stats + 128, gamma2, beta2, invN, sb + 128);

    final_kernel<<<1024, 256>>>(buf2, sb + 128, features, out, total4);
}

// round 8
// speedup vs baseline: 1.3861x; 1.3861x over previous
#include <cuda_runtime.h>
#include <cuda_bf16.h>
#include <cstdint>

#define CH    64
#define EPSV  1e-5f
#define MAXN  100000
#define MAXK  27

// ================= scratch (__device__ globals, alloc-free) =================
__device__ float g_buf1[MAXN * CH];      // conv1 raw output (fp32)
__device__ float g_buf2[MAXN * CH];      // conv2 raw output (fp32)
__device__ float g_stats[256];           // [sum1, sumsq1, sum2, sumsq2]
__device__ float g_sb[256];              // [scale1, shift1, scale2, shift2]
__device__ __align__(16) __nv_bfloat16 g_fhi[MAXN * CH];
__device__ __align__(16) __nv_bfloat16 g_flo[MAXN * CH];
// W pre-packed in fused mma B-fragment order: uint4{bh_reg0, bh_reg1, bl_reg0, bl_reg1}
__device__ __align__(16) uint4 g_Wf1[MAXK * 1024];
__device__ __align__(16) uint4 g_Wf2[MAXK * 1024];

// ================= helpers =================
__device__ __forceinline__ uint32_t smem_u32(const void* p) {
    uint32_t a;
    asm("{ .reg .u64 t; cvta.to.shared.u64 t, %1; cvt.u32.u64 %0, t; }" : "=r"(a) : "l"(p));
    return a;
}

__device__ __forceinline__ void ldmatrix_x4(uint32_t* r, uint32_t addr) {
    asm volatile("ldmatrix.sync.aligned.m8n8.x4.shared.b16 {%0,%1,%2,%3}, [%4];"
                 : "=r"(r[0]), "=r"(r[1]), "=r"(r[2]), "=r"(r[3]) : "r"(addr));
}

__device__ __forceinline__ void mma16816(float* c, const uint32_t* a,
                                         uint32_t b0, uint32_t b1) {
    asm volatile(
        "mma.sync.aligned.m16n8k16.row.col.f32.bf16.bf16.f32 "
        "{%0,%1,%2,%3}, {%4,%5,%6,%7}, {%8,%9}, {%0,%1,%2,%3};"
        : "+f"(c[0]), "+f"(c[1]), "+f"(c[2]), "+f"(c[3])
        : "r"(a[0]), "r"(a[1]), "r"(a[2]), "r"(a[3]), "r"(b0), "r"(b1));
}

// SMEM layout for conv kernel (dynamic)
#define OFF_AH   0
#define OFF_AL   16384
#define OFF_B    32768
#define OFF_IIDX 49152
#define OFF_OIDX 49664
#define SMEM_BYTES 50176

// ================= kernels =================

// W[k][cin][cout] fp32 -> fused bf16 hi/lo B-fragments, column-permuted for red.v4.
// uint4 index q: lane = q&31, nt = (q>>5)&7, ks = q>>8
// reg r in {0,1}: k0 = ks*16 + (lane&3)*2 + r*8 ; local col l = lane>>2
// source col n = 16*(nt>>1) + 4*(l>>1) + 2*(nt&1) + (l&1)
// Also zeroes g_stats (block 0).
__global__ __launch_bounds__(256)
void prep_w_kernel(const float* __restrict__ W1, const float* __restrict__ W2, int K)
{
    const int k     = blockIdx.x;
    const int layer = blockIdx.y;
    const float* Wk = (layer ? W2 : W1) + (size_t)k * 4096;
    uint4* dst = (layer ? g_Wf2 : g_Wf1) + (size_t)k * 1024;

    if (blockIdx.x == 0 && blockIdx.y == 0 && threadIdx.x < 64)
        reinterpret_cast<float4*>(g_stats)[threadIdx.x] =
            make_float4(0.f, 0.f, 0.f, 0.f);

    for (int q = threadIdx.x; q < 1024; q += 256) {
        const int lane = q & 31;
        const int nt   = (q >> 5) & 7;
        const int ks   = q >> 8;
        const int l    = lane >> 2;
        const int n    = 16 * (nt >> 1) + 4 * (l >> 1) + 2 * (nt & 1) + (l & 1);
        uint32_t r[4];
        #pragma unroll
        for (int reg = 0; reg < 2; ++reg) {
            const int k0   = ks * 16 + (lane & 3) * 2 + reg * 8;
            const float v0 = Wk[k0 * 64 + n];
            const float v1 = Wk[(k0 + 1) * 64 + n];
            const __nv_bfloat16 h0 = __float2bfloat16(v0);
            const __nv_bfloat16 h1 = __float2bfloat16(v1);
            const __nv_bfloat16 l0 = __float2bfloat16(v0 - __bfloat162float(h0));
            const __nv_bfloat16 l1 = __float2bfloat16(v1 - __bfloat162float(h1));
            r[reg]     = (uint32_t)__bfloat16_as_ushort(h0)
                       | ((uint32_t)__bfloat16_as_ushort(h1) << 16);
            r[2 + reg] = (uint32_t)__bfloat16_as_ushort(l0)
                       | ((uint32_t)__bfloat16_as_ushort(l1) << 16);
        }
        dst[q] = make_uint4(r[0], r[1], r[2], r[3]);
    }
}

// fp32 rows -> bf16 hi/lo split (optional fused relu(bn) via sb).
// When z1 != nullptr also zero-fills buf rows (fused zero pass).
__global__ __launch_bounds__(256)
void prep_feat_kernel(const float* __restrict__ src, const float* __restrict__ sb,
                      float* __restrict__ z1, float* __restrict__ z2, int N)
{
    const int gid = blockIdx.x * blockDim.x + threadIdx.x;
    if (gid >= N * 8) return;
    const int row = gid >> 3;
    const int c0  = (gid & 7) * 8;

    const float4 v0 = reinterpret_cast<const float4*>(src + (size_t)row * 64 + c0)[0];
    const float4 v1 = reinterpret_cast<const float4*>(src + (size_t)row * 64 + c0)[1];
    float v[8] = {v0.x, v0.y, v0.z, v0.w, v1.x, v1.y, v1.z, v1.w};

    if (sb) {
        #pragma unroll
        for (int j = 0; j < 8; ++j)
            v[j] = fmaxf(fmaf(v[j], sb[c0 + j], sb[64 + c0 + j]), 0.f);
    }

    union { __nv_bfloat16 h[8]; uint4 u; } uh, ul;
    #pragma unroll
    for (int j = 0; j < 8; ++j) {
        const __nv_bfloat16 hi = __float2bfloat16(v[j]);
        uh.h[j] = hi;
        ul.h[j] = __float2bfloat16(v[j] - __bfloat162float(hi));
    }
    reinterpret_cast<uint4*>(g_fhi)[(size_t)row * 8 + (c0 >> 3)] = uh.u;
    reinterpret_cast<uint4*>(g_flo)[(size_t)row * 8 + (c0 >> 3)] = ul.u;

    if (z1) {
        const float4 z = make_float4(0.f, 0.f, 0.f, 0.f);
        const size_t f4 = (size_t)row * 16 + (c0 >> 2);
        reinterpret_cast<float4*>(z1)[f4]     = z;
        reinterpret_cast<float4*>(z1)[f4 + 1] = z;
        reinterpret_cast<float4*>(z2)[f4]     = z;
        reinterpret_cast<float4*>(z2)[f4 + 1] = z;
    }
}

// gather -> mma.sync bf16-split -> red.v4 scatter
// 8 warps arranged 4(row)x2(col); each warp: 32 rows x 32 cols.
// B fragments fused (hi+lo in one uint4 -> single LDS.128 per (ks,nt)).
__global__ __launch_bounds__(256)
void conv_mma_kernel(const __nv_bfloat16* __restrict__ fhi,
                     const __nv_bfloat16* __restrict__ flo,
                     const uint4* __restrict__ Wf,
                     const int* __restrict__ in_maps,
                     const int* __restrict__ out_maps,
                     float* __restrict__ out,
                     int M)
{
    extern __shared__ char sm[];
    char*  Ah   = sm + OFF_AH;
    char*  Al   = sm + OFF_AL;
    uint4* B    = reinterpret_cast<uint4*>(sm + OFF_B);
    int*   iidx = reinterpret_cast<int*>(sm + OFF_IIDX);
    int*   oidx = reinterpret_cast<int*>(sm + OFF_OIDX);

    const int t    = threadIdx.x;
    const int lane = t & 31;
    const int w    = t >> 5;
    const int wr   = w >> 1;      // row group 0..3
    const int wc   = w & 1;       // col group 0..1
    const int k    = blockIdx.y;
    const int m0   = blockIdx.x * 128;

    // maps
    if (t < 128) {
        const int m = m0 + t;
        iidx[t] = (m < M) ? in_maps [(size_t)k * M + m] : -1;
        oidx[t] = (m < M) ? out_maps[(size_t)k * M + m] : -1;
    }
    // B-fragment copy (1024 uint4)
    {
        const uint4* s = Wf + (size_t)k * 1024;
        B[t]       = s[t];
        B[t + 256] = s[t + 256];
        B[t + 512] = s[t + 512];
        B[t + 768] = s[t + 768];
    }
    __syncthreads();

    // gather A (hi/lo): 8 lanes per row, one 16B chunk each (coalesced rows).
    {
        const int c = t & 7;          // chunk 0..7
        const int g = t >> 3;         // row sub-index 0..31
        const uint4 z = make_uint4(0, 0, 0, 0);
        #pragma unroll
        for (int it = 0; it < 4; ++it) {
            const int row = it * 32 + g;
            const int src = iidx[row];
            uint4 vh = z, vl = z;
            if (src >= 0) {
                vh = reinterpret_cast<const uint4*>(fhi)[(size_t)src * 8 + c];
                vl = reinterpret_cast<const uint4*>(flo)[(size_t)src * 8 + c];
            }
            const int d = row * 128 + ((c ^ (row & 7)) << 4);
            *reinterpret_cast<uint4*>(Ah + d) = vh;
            *reinterpret_cast<uint4*>(Al + d) = vl;
        }
    }
    __syncthreads();

    // MMA mainloop: warp covers rows [wr*32, wr*32+32), cols [wc*32, wc*32+32)
    float acc[2][4][4];
    #pragma unroll
    for (int rt = 0; rt < 2; ++rt)
        #pragma unroll
        for (int nl = 0; nl < 4; ++nl)
            #pragma unroll
            for (int j = 0; j < 4; ++j) acc[rt][nl][j] = 0.f;

    const uint32_t ahb = smem_u32(Ah);
    const uint32_t alb = smem_u32(Al);
    const int half = lane >> 4;

    #pragma unroll
    for (int ks = 0; ks < 4; ++ks) {
        uint32_t aH[2][4], aL[2][4];
        #pragma unroll
        for (int rt = 0; rt < 2; ++rt) {
            const int row   = wr * 32 + rt * 16 + (lane & 15);
            const int chunk = ks * 2 + half;
            const uint32_t off = row * 128 + ((chunk ^ (row & 7)) << 4);
            ldmatrix_x4(aH[rt], ahb + off);
            ldmatrix_x4(aL[rt], alb + off);
        }
        #pragma unroll
        for (int nl = 0; nl < 4; ++nl) {
            const int nt = wc * 4 + nl;
            const uint4 b = B[(ks * 8 + nt) * 32 + lane];
            #pragma unroll
            for (int rt = 0; rt < 2; ++rt) {
                mma16816(acc[rt][nl], aH[rt], b.x, b.y);
                mma16816(acc[rt][nl], aH[rt], b.z, b.w);
                mma16816(acc[rt][nl], aL[rt], b.x, b.y);
            }
        }
    }

    // scatter via red.v4: permuted cols -> pair (2p,2p+1) lands contiguously
    #pragma unroll
    for (int rt = 0; rt < 2; ++rt) {
        const int r0 = wr * 32 + rt * 16 + (lane >> 2);
        const int o0 = oidx[r0];
        const int o1 = oidx[r0 + 8];
        const int cb = 4 * (lane & 3);
        #pragma unroll
        for (int p = 0; p < 2; ++p) {
            const int col = 16 * (wc * 2 + p) + cb;
            if (o0 >= 0) {
                asm volatile("red.global.add.v4.f32 [%0], {%1, %2, %3, %4};"
                    :: "l"(out + (size_t)o0 * 64 + col),
                       "f"(acc[rt][2*p][0]), "f"(acc[rt][2*p][1]),
                       "f"(acc[rt][2*p+1][0]), "f"(acc[rt][2*p+1][1]) : "memory");
            }
            if (o1 >= 0) {
                asm volatile("red.global.add.v4.f32 [%0], {%1, %2, %3, %4};"
                    :: "l"(out + (size_t)o1 * 64 + col),
                       "f"(acc[rt][2*p][2]), "f"(acc[rt][2*p][3]),
                       "f"(acc[rt][2*p+1][2]), "f"(acc[rt][2*p+1][3]) : "memory");
            }
        }
    }
}

// per-channel sum / sumsq
__global__ __launch_bounds__(256)
void stats_kernel(const float* __restrict__ x, int N, float* __restrict__ sums)
{
    const int t   = threadIdx.x;
    const int col = t & 63;
    const int rg  = t >> 6;
    float s = 0.f, ss = 0.f;
    for (int r = blockIdx.x * 4 + rg; r < N; r += gridDim.x * 4) {
        const float v = x[(size_t)r * 64 + col];
        s += v; ss += v * v;
    }
    __shared__ float sh[512];
    sh[t] = s; sh[256 + t] = ss;
    __syncthreads();
    if (t < 64) {
        float S  = sh[t]       + sh[t + 64]       + sh[t + 128]       + sh[t + 192];
        float SS = sh[256 + t] + sh[256 + t + 64] + sh[256 + t + 128] + sh[256 + t + 192];
        atomicAdd(&sums[t],      S);
        atomicAdd(&sums[64 + t], SS);
    }
}

__global__ void finalize_kernel(const float* __restrict__ sums,
                                const float* __restrict__ gamma,
                                const float* __restrict__ beta,
                                float invN, float* __restrict__ sb)
{
    const int t = threadIdx.x;
    const float mean = sums[t] * invN;
    const float var  = fmaxf(sums[64 + t] * invN - mean * mean, 0.f);
    const float s    = gamma[t] * rsqrtf(var + EPSV);
    sb[t]      = s;
    sb[64 + t] = beta[t] - mean * s;
}

__global__ __launch_bounds__(256)
void final_kernel(const float* __restrict__ conv2, const float* __restrict__ sb2,
                  const float* __restrict__ feat, float* __restrict__ out, int n4)
{
    int i = blockIdx.x * blockDim.x + threadIdx.x;
    for (int j = i; j < n4; j += gridDim.x * blockDim.x) {
        const float4 v = reinterpret_cast<const float4*>(conv2)[j];
        const float4 f = reinterpret_cast<const float4*>(feat)[j];
        const int c0 = (j & 15) * 4;
        float4 r;
        r.x = fmaxf(fmaf(v.x, sb2[c0 + 0], sb2[64 + c0 + 0]) + f.x, 0.f);
        r.y = fmaxf(fmaf(v.y, sb2[c0 + 1], sb2[64 + c0 + 1]) + f.y, 0.f);
        r.z = fmaxf(fmaf(v.z, sb2[c0 + 2], sb2[64 + c0 + 2]) + f.z, 0.f);
        r.w = fmaxf(fmaf(v.w, sb2[c0 + 3], sb2[64 + c0 + 3]) + f.w, 0.f);
        reinterpret_cast<float4*>(out)[j] = r;
    }
}

// ================= launcher =================
extern "C" void kernel_launch(void* const* d_in, const int* in_sizes, int n_in,
                              void* d_out, int out_size)
{
    const float* features = (const float*)d_in[0];
    const float* W1       = (const float*)d_in[1];
    const float* gamma1   = (const float*)d_in[2];
    const float* beta1    = (const float*)d_in[3];
    const float* W2       = (const float*)d_in[4];
    const float* gamma2   = (const float*)d_in[5];
    const float* beta2    = (const float*)d_in[6];
    const int*   in_maps  = (const int*)d_in[7];
    const int*   out_maps = (const int*)d_in[8];
    float*       out      = (float*)d_out;

    const int N = in_sizes[0] / CH;
    const int K = in_sizes[1] / (CH * CH);
    const int M = in_sizes[7] / K;

    float* buf1;  cudaGetSymbolAddress((void**)&buf1,  g_buf1);
    float* buf2;  cudaGetSymbolAddress((void**)&buf2,  g_buf2);
    float* stats; cudaGetSymbolAddress((void**)&stats, g_stats);
    float* sb;    cudaGetSymbolAddress((void**)&sb,    g_sb);
    __nv_bfloat16 *fhi, *flo;
    cudaGetSymbolAddress((void**)&fhi, g_fhi);
    cudaGetSymbolAddress((void**)&flo, g_flo);
    uint4 *wf1, *wf2;
    cudaGetSymbolAddress((void**)&wf1, g_Wf1);
    cudaGetSymbolAddress((void**)&wf2, g_Wf2);

    cudaFuncSetAttribute(conv_mma_kernel,
                         cudaFuncAttributeMaxDynamicSharedMemorySize, SMEM_BYTES);

    const int total4 = N * (CH / 4);
    const float invN = 1.0f / (float)N;
    const dim3 convGrid((M + 127) / 128, K);
    const int pfBlocks = (N * 8 + 255) / 256;

    prep_w_kernel<<<dim3(K, 2), 256>>>(W1, W2, K);

    // conv1 (prep also zeroes buf1/buf2)
    prep_feat_kernel<<<pfBlocks, 256>>>(features, nullptr, buf1, buf2, N);
    conv_mma_kernel<<<convGrid, 256, SMEM_BYTES>>>(fhi, flo, wf1,
                                                   in_maps, out_maps, buf1, M);
    stats_kernel<<<512, 256>>>(buf1, N, stats);
    finalize_kernel<<<1, 64>>>(stats, gamma1, beta1, invN, sb);

    // conv2 (BN1+ReLU fused into split pass)
    prep_feat_kernel<<<pfBlocks, 256>>>(buf1, sb, nullptr, nullptr, N);
    conv_mma_kernel<<<convGrid, 256, SMEM_BYTES>>>(fhi, flo, wf2,
                                                   in_maps, out_maps, buf2, M);
    stats_kernel<<<512, 256>>>(buf2, N, stats + 128);
    finalize_kernel<<<1, 64>>>(stats + 128, gamma2, beta2, invN, sb + 128);

    final_kernel<<<1024, 256>>>(buf2, sb + 128, features, out, total4);
}

// round 9
// speedup vs baseline: 1.6986x; 1.2254x over previous
#include <cuda_runtime.h>
#include <cuda_bf16.h>
#include <cstdint>

#define CH    64
#define EPSV  1e-5f
#define MAXN  100000
#define MAXK  27

// ================= scratch (__device__ globals, alloc-free) =================
__device__ float g_buf1[MAXN * CH];      // conv1 raw output (fp32)
__device__ float g_buf2[MAXN * CH];      // conv2 raw output (fp32)
__device__ float g_stats[256];           // [sum1, sumsq1, sum2, sumsq2]
__device__ float g_sb[256];              // [scale1, shift1, scale2, shift2]
__device__ __align__(16) __nv_bfloat16 g_fhi[MAXN * CH];
__device__ __align__(16) __nv_bfloat16 g_flo[MAXN * CH];
// W pre-packed in fused mma B-fragment order: uint4{bh_reg0, bh_reg1, bl_reg0, bl_reg1}
__device__ __align__(16) uint4 g_Wf1[MAXK * 1024];
__device__ __align__(16) uint4 g_Wf2[MAXK * 1024];

// ================= helpers =================
__device__ __forceinline__ uint32_t smem_u32(const void* p) {
    uint32_t a;
    asm("{ .reg .u64 t; cvta.to.shared.u64 t, %1; cvt.u32.u64 %0, t; }" : "=r"(a) : "l"(p));
    return a;
}

__device__ __forceinline__ void ldmatrix_x4(uint32_t* r, uint32_t addr) {
    asm volatile("ldmatrix.sync.aligned.m8n8.x4.shared.b16 {%0,%1,%2,%3}, [%4];"
                 : "=r"(r[0]), "=r"(r[1]), "=r"(r[2]), "=r"(r[3]) : "r"(addr));
}

__device__ __forceinline__ void mma16816(float* c, const uint32_t* a,
                                         uint32_t b0, uint32_t b1) {
    asm volatile(
        "mma.sync.aligned.m16n8k16.row.col.f32.bf16.bf16.f32 "
        "{%0,%1,%2,%3}, {%4,%5,%6,%7}, {%8,%9}, {%0,%1,%2,%3};"
        : "+f"(c[0]), "+f"(c[1]), "+f"(c[2]), "+f"(c[3])
        : "r"(a[0]), "r"(a[1]), "r"(a[2]), "r"(a[3]), "r"(b0), "r"(b1));
}

__device__ __forceinline__ void cp_async16(uint32_t dst, const void* src, int sz) {
    asm volatile("cp.async.cg.shared.global [%0], [%1], 16, %2;"
                 :: "r"(dst), "l"(src), "r"(sz) : "memory");
}

// SMEM layout for conv kernel (dynamic)
#define OFF_AH   0
#define OFF_AL   16384
#define OFF_B    32768
#define OFF_IIDX 49152
#define OFF_OIDX 49664
#define SMEM_BYTES 50176

// ================= kernels =================

// W[k][cin][cout] fp32 -> fused bf16 hi/lo B-fragments, column-permuted for red.v4.
// Also zeroes g_stats (block 0).
__global__ __launch_bounds__(256)
void prep_w_kernel(const float* __restrict__ W1, const float* __restrict__ W2, int K)
{
    const int k     = blockIdx.x;
    const int layer = blockIdx.y;
    const float* Wk = (layer ? W2 : W1) + (size_t)k * 4096;
    uint4* dst = (layer ? g_Wf2 : g_Wf1) + (size_t)k * 1024;

    if (blockIdx.x == 0 && blockIdx.y == 0 && threadIdx.x < 64)
        reinterpret_cast<float4*>(g_stats)[threadIdx.x] =
            make_float4(0.f, 0.f, 0.f, 0.f);

    for (int q = threadIdx.x; q < 1024; q += 256) {
        const int lane = q & 31;
        const int nt   = (q >> 5) & 7;
        const int ks   = q >> 8;
        const int l    = lane >> 2;
        const int n    = 16 * (nt >> 1) + 4 * (l >> 1) + 2 * (nt & 1) + (l & 1);
        uint32_t r[4];
        #pragma unroll
        for (int reg = 0; reg < 2; ++reg) {
            const int k0   = ks * 16 + (lane & 3) * 2 + reg * 8;
            const float v0 = Wk[k0 * 64 + n];
            const float v1 = Wk[(k0 + 1) * 64 + n];
            const __nv_bfloat16 h0 = __float2bfloat16(v0);
            const __nv_bfloat16 h1 = __float2bfloat16(v1);
            const __nv_bfloat16 l0 = __float2bfloat16(v0 - __bfloat162float(h0));
            const __nv_bfloat16 l1 = __float2bfloat16(v1 - __bfloat162float(h1));
            r[reg]     = (uint32_t)__bfloat16_as_ushort(h0)
                       | ((uint32_t)__bfloat16_as_ushort(h1) << 16);
            r[2 + reg] = (uint32_t)__bfloat16_as_ushort(l0)
                       | ((uint32_t)__bfloat16_as_ushort(l1) << 16);
        }
        dst[q] = make_uint4(r[0], r[1], r[2], r[3]);
    }
}

// fp32 rows -> bf16 hi/lo split (optional fused relu(bn) via sb).
// When z1 != nullptr also zero-fills buf rows (fused zero pass).
__global__ __launch_bounds__(256)
void prep_feat_kernel(const float* __restrict__ src, const float* __restrict__ sb,
                      float* __restrict__ z1, float* __restrict__ z2, int N)
{
    const int gid = blockIdx.x * blockDim.x + threadIdx.x;
    if (gid >= N * 8) return;
    const int row = gid >> 3;
    const int c0  = (gid & 7) * 8;

    const float4 v0 = reinterpret_cast<const float4*>(src + (size_t)row * 64 + c0)[0];
    const float4 v1 = reinterpret_cast<const float4*>(src + (size_t)row * 64 + c0)[1];
    float v[8] = {v0.x, v0.y, v0.z, v0.w, v1.x, v1.y, v1.z, v1.w};

    if (sb) {
        #pragma unroll
        for (int j = 0; j < 8; ++j)
            v[j] = fmaxf(fmaf(v[j], sb[c0 + j], sb[64 + c0 + j]), 0.f);
    }

    union { __nv_bfloat16 h[8]; uint4 u; } uh, ul;
    #pragma unroll
    for (int j = 0; j < 8; ++j) {
        const __nv_bfloat16 hi = __float2bfloat16(v[j]);
        uh.h[j] = hi;
        ul.h[j] = __float2bfloat16(v[j] - __bfloat162float(hi));
    }
    reinterpret_cast<uint4*>(g_fhi)[(size_t)row * 8 + (c0 >> 3)] = uh.u;
    reinterpret_cast<uint4*>(g_flo)[(size_t)row * 8 + (c0 >> 3)] = ul.u;

    if (z1) {
        const float4 z = make_float4(0.f, 0.f, 0.f, 0.f);
        const size_t f4 = (size_t)row * 16 + (c0 >> 2);
        reinterpret_cast<float4*>(z1)[f4]     = z;
        reinterpret_cast<float4*>(z1)[f4 + 1] = z;
        reinterpret_cast<float4*>(z2)[f4]     = z;
        reinterpret_cast<float4*>(z2)[f4 + 1] = z;
    }
}

// gather (cp.async) -> mma.sync bf16-split -> red.v4 scatter
// 8 warps arranged 4(row)x2(col); each warp: 32 rows x 32 cols.
__global__ __launch_bounds__(256)
void conv_mma_kernel(const __nv_bfloat16* __restrict__ fhi,
                     const __nv_bfloat16* __restrict__ flo,
                     const uint4* __restrict__ Wf,
                     const int* __restrict__ in_maps,
                     const int* __restrict__ out_maps,
                     float* __restrict__ out,
                     int M)
{
    extern __shared__ char sm[];
    char*  Ah   = sm + OFF_AH;
    char*  Al   = sm + OFF_AL;
    uint4* B    = reinterpret_cast<uint4*>(sm + OFF_B);
    int*   iidx = reinterpret_cast<int*>(sm + OFF_IIDX);
    int*   oidx = reinterpret_cast<int*>(sm + OFF_OIDX);

    const int t    = threadIdx.x;
    const int lane = t & 31;
    const int w    = t >> 5;
    const int wr   = w >> 1;      // row group 0..3
    const int wc   = w & 1;       // col group 0..1
    const int k    = blockIdx.y;
    const int m0   = blockIdx.x * 128;

    // maps
    if (t < 128) {
        const int m = m0 + t;
        iidx[t] = (m < M) ? in_maps [(size_t)k * M + m] : -1;
        oidx[t] = (m < M) ? out_maps[(size_t)k * M + m] : -1;
    }
    // B-fragment copy (1024 uint4)
    {
        const uint4* s = Wf + (size_t)k * 1024;
        B[t]       = s[t];
        B[t + 256] = s[t + 256];
        B[t + 512] = s[t + 512];
        B[t + 768] = s[t + 768];
    }
    __syncthreads();

    const uint32_t ahb = smem_u32(Ah);
    const uint32_t alb = smem_u32(Al);

    // gather A (hi/lo) via cp.async: 8 lanes per row, one 16B chunk each.
    {
        const int c = t & 7;          // chunk 0..7
        const int g = t >> 3;         // row sub-index 0..31
        #pragma unroll
        for (int it = 0; it < 4; ++it) {
            const int row = it * 32 + g;
            const int src = iidx[row];
            const int sz  = (src >= 0) ? 16 : 0;
            const size_t base = (size_t)(src >= 0 ? src : 0) * 8 + c;
            const uint32_t d = (uint32_t)(row * 128 + ((c ^ (row & 7)) << 4));
            cp_async16(ahb + d, reinterpret_cast<const uint4*>(fhi) + base, sz);
            cp_async16(alb + d, reinterpret_cast<const uint4*>(flo) + base, sz);
        }
        asm volatile("cp.async.commit_group;" ::: "memory");
        asm volatile("cp.async.wait_group 0;" ::: "memory");
    }
    __syncthreads();

    // MMA mainloop: warp covers rows [wr*32, wr*32+32), cols [wc*32, wc*32+32)
    float acc[2][4][4];
    #pragma unroll
    for (int rt = 0; rt < 2; ++rt)
        #pragma unroll
        for (int nl = 0; nl < 4; ++nl)
            #pragma unroll
            for (int j = 0; j < 4; ++j) acc[rt][nl][j] = 0.f;

    const int half = lane >> 4;

    #pragma unroll
    for (int ks = 0; ks < 4; ++ks) {
        uint32_t aH[2][4], aL[2][4];
        #pragma unroll
        for (int rt = 0; rt < 2; ++rt) {
            const int row   = wr * 32 + rt * 16 + (lane & 15);
            const int chunk = ks * 2 + half;
            const uint32_t off = row * 128 + ((chunk ^ (row & 7)) << 4);
            ldmatrix_x4(aH[rt], ahb + off);
            ldmatrix_x4(aL[rt], alb + off);
        }
        #pragma unroll
        for (int nl = 0; nl < 4; ++nl) {
            const int nt = wc * 4 + nl;
            const uint4 b = B[(ks * 8 + nt) * 32 + lane];
            #pragma unroll
            for (int rt = 0; rt < 2; ++rt) {
                mma16816(acc[rt][nl], aH[rt], b.x, b.y);
                mma16816(acc[rt][nl], aH[rt], b.z, b.w);
                mma16816(acc[rt][nl], aL[rt], b.x, b.y);
            }
        }
    }

    // scatter via red.v4: permuted cols -> pair (2p,2p+1) lands contiguously
    #pragma unroll
    for (int rt = 0; rt < 2; ++rt) {
        const int r0 = wr * 32 + rt * 16 + (lane >> 2);
        const int o0 = oidx[r0];
        const int o1 = oidx[r0 + 8];
        const int cb = 4 * (lane & 3);
        #pragma unroll
        for (int p = 0; p < 2; ++p) {
            const int col = 16 * (wc * 2 + p) + cb;
            if (o0 >= 0) {
                asm volatile("red.global.add.v4.f32 [%0], {%1, %2, %3, %4};"
                    :: "l"(out + (size_t)o0 * 64 + col),
                       "f"(acc[rt][2*p][0]), "f"(acc[rt][2*p][1]),
                       "f"(acc[rt][2*p+1][0]), "f"(acc[rt][2*p+1][1]) : "memory");
            }
            if (o1 >= 0) {
                asm volatile("red.global.add.v4.f32 [%0], {%1, %2, %3, %4};"
                    :: "l"(out + (size_t)o1 * 64 + col),
                       "f"(acc[rt][2*p][2]), "f"(acc[rt][2*p][3]),
                       "f"(acc[rt][2*p+1][2]), "f"(acc[rt][2*p+1][3]) : "memory");
            }
        }
    }
}

// per-channel sum / sumsq, float4-vectorized (4 channels per thread)
__global__ __launch_bounds__(256)
void stats_kernel(const float* __restrict__ x, int N, float* __restrict__ sums)
{
    const int t  = threadIdx.x;
    const int cg = t & 15;        // channel group (4 channels)
    const int rg = t >> 4;        // 16 row lanes per block
    float s0 = 0.f, s1 = 0.f, s2 = 0.f, s3 = 0.f;
    float q0 = 0.f, q1 = 0.f, q2 = 0.f, q3 = 0.f;
    const int stride = gridDim.x * 16;
    for (int r = blockIdx.x * 16 + rg; r < N; r += stride) {
        const float4 v = reinterpret_cast<const float4*>(x + (size_t)r * 64 + cg * 4)[0];
        s0 += v.x; s1 += v.y; s2 += v.z; s3 += v.w;
        q0 += v.x * v.x; q1 += v.y * v.y; q2 += v.z * v.z; q3 += v.w * v.w;
    }
    __shared__ float sh[256 * 8];
    float* my = sh + t * 8;
    my[0] = s0; my[1] = s1; my[2] = s2; my[3] = s3;
    my[4] = q0; my[5] = q1; my[6] = q2; my[7] = q3;
    __syncthreads();
    if (t < 64) {
        const int cgi = t >> 2;   // which channel group
        const int j   = t & 3;    // which channel within group
        float S = 0.f, Q = 0.f;
        #pragma unroll
        for (int r = 0; r < 16; ++r) {
            const float* p = sh + (r * 16 + cgi) * 8 + j;
            S += p[0];
            Q += p[4];
        }
        atomicAdd(&sums[t],      S);
        atomicAdd(&sums[64 + t], Q);
    }
}

__global__ void finalize_kernel(const float* __restrict__ sums,
                                const float* __restrict__ gamma,
                                const float* __restrict__ beta,
                                float invN, float* __restrict__ sb)
{
    const int t = threadIdx.x;
    const float mean = sums[t] * invN;
    const float var  = fmaxf(sums[64 + t] * invN - mean * mean, 0.f);
    const float s    = gamma[t] * rsqrtf(var + EPSV);
    sb[t]      = s;
    sb[64 + t] = beta[t] - mean * s;
}

__global__ __launch_bounds__(256)
void final_kernel(const float* __restrict__ conv2, const float* __restrict__ sb2,
                  const float* __restrict__ feat, float* __restrict__ out, int n4)
{
    int i = blockIdx.x * blockDim.x + threadIdx.x;
    for (int j = i; j < n4; j += gridDim.x * blockDim.x) {
        const float4 v = reinterpret_cast<const float4*>(conv2)[j];
        const float4 f = reinterpret_cast<const float4*>(feat)[j];
        const int c0 = (j & 15) * 4;
        float4 r;
        r.x = fmaxf(fmaf(v.x, sb2[c0 + 0], sb2[64 + c0 + 0]) + f.x, 0.f);
        r.y = fmaxf(fmaf(v.y, sb2[c0 + 1], sb2[64 + c0 + 1]) + f.y, 0.f);
        r.z = fmaxf(fmaf(v.z, sb2[c0 + 2], sb2[64 + c0 + 2]) + f.z, 0.f);
        r.w = fmaxf(fmaf(v.w, sb2[c0 + 3], sb2[64 + c0 + 3]) + f.w, 0.f);
        reinterpret_cast<float4*>(out)[j] = r;
    }
}

// ================= launcher =================
extern "C" void kernel_launch(void* const* d_in, const int* in_sizes, int n_in,
                              void* d_out, int out_size)
{
    const float* features = (const float*)d_in[0];
    const float* W1       = (const float*)d_in[1];
    const float* gamma1   = (const float*)d_in[2];
    const float* beta1    = (const float*)d_in[3];
    const float* W2       = (const float*)d_in[4];
    const float* gamma2   = (const float*)d_in[5];
    const float* beta2    = (const float*)d_in[6];
    const int*   in_maps  = (const int*)d_in[7];
    const int*   out_maps = (const int*)d_in[8];
    float*       out      = (float*)d_out;

    const int N = in_sizes[0] / CH;
    const int K = in_sizes[1] / (CH * CH);
    const int M = in_sizes[7] / K;

    float* buf1;  cudaGetSymbolAddress((void**)&buf1,  g_buf1);
    float* buf2;  cudaGetSymbolAddress((void**)&buf2,  g_buf2);
    float* stats; cudaGetSymbolAddress((void**)&stats, g_stats);
    float* sb;    cudaGetSymbolAddress((void**)&sb,    g_sb);
    __nv_bfloat16 *fhi, *flo;
    cudaGetSymbolAddress((void**)&fhi, g_fhi);
    cudaGetSymbolAddress((void**)&flo, g_flo);
    uint4 *wf1, *wf2;
    cudaGetSymbolAddress((void**)&wf1, g_Wf1);
    cudaGetSymbolAddress((void**)&wf2, g_Wf2);

    cudaFuncSetAttribute(conv_mma_kernel,
                         cudaFuncAttributeMaxDynamicSharedMemorySize, SMEM_BYTES);

    const int total4 = N * (CH / 4);
    const float invN = 1.0f / (float)N;
    const dim3 convGrid((M + 127) / 128, K);
    const int pfBlocks = (N * 8 + 255) / 256;

    prep_w_kernel<<<dim3(K, 2), 256>>>(W1, W2, K);

    // conv1 (prep also zeroes buf1/buf2)
    prep_feat_kernel<<<pfBlocks, 256>>>(features, nullptr, buf1, buf2, N);
    conv_mma_kernel<<<convGrid, 256, SMEM_BYTES>>>(fhi, flo, wf1,
                                                   in_maps, out_maps, buf1, M);
    stats_kernel<<<512, 256>>>(buf1, N, stats);
    finalize_kernel<<<1, 64>>>(stats, gamma1, beta1, invN, sb);

    // conv2 (BN1+ReLU fused into split pass)
    prep_feat_kernel<<<pfBlocks, 256>>>(buf1, sb, nullptr, nullptr, N);
    conv_mma_kernel<<<convGrid, 256, SMEM_BYTES>>>(fhi, flo, wf2,
                                                   in_maps, out_maps, buf2, M);
    stats_kernel<<<512, 256>>>(buf2, N, stats + 128);
    finalize_kernel<<<1, 64>>>(stats + 128, gamma2, beta2, invN, sb + 128);

    final_kernel<<<1024, 256>>>(buf2, sb + 128, features, out, total4);
}

// round 10
// speedup vs baseline: 1.7226x; 1.0141x over previous
#include <cuda_runtime.h>
#include <cuda_bf16.h>
#include <cstdint>

#define CH    64
#define EPSV  1e-5f
#define MAXN  100000
#define MAXK  27

// ================= scratch (__device__ globals, alloc-free) =================
__device__ float g_buf1[MAXN * CH];      // conv1 raw output (fp32)
__device__ float g_buf2[MAXN * CH];      // conv2 raw output (fp32)
__device__ float g_stats[256];           // [sum1, sumsq1, sum2, sumsq2]
__device__ float g_sb[256];              // [scale1, shift1, scale2, shift2]
__device__ unsigned int g_cnt[2];        // stats completion tickets
__device__ __align__(16) __nv_bfloat16 g_fhi[MAXN * CH];
__device__ __align__(16) __nv_bfloat16 g_flo[MAXN * CH];
// W pre-packed in fused mma B-fragment order: uint4{bh_reg0, bh_reg1, bl_reg0, bl_reg1}
__device__ __align__(16) uint4 g_Wf1[MAXK * 1024];
__device__ __align__(16) uint4 g_Wf2[MAXK * 1024];

// ================= helpers =================
__device__ __forceinline__ uint32_t smem_u32(const void* p) {
    uint32_t a;
    asm("{ .reg .u64 t; cvta.to.shared.u64 t, %1; cvt.u32.u64 %0, t; }" : "=r"(a) : "l"(p));
    return a;
}

__device__ __forceinline__ void ldmatrix_x4(uint32_t* r, uint32_t addr) {
    asm volatile("ldmatrix.sync.aligned.m8n8.x4.shared.b16 {%0,%1,%2,%3}, [%4];"
                 : "=r"(r[0]), "=r"(r[1]), "=r"(r[2]), "=r"(r[3]) : "r"(addr));
}

__device__ __forceinline__ void mma16816(float* c, const uint32_t* a,
                                         uint32_t b0, uint32_t b1) {
    asm volatile(
        "mma.sync.aligned.m16n8k16.row.col.f32.bf16.bf16.f32 "
        "{%0,%1,%2,%3}, {%4,%5,%6,%7}, {%8,%9}, {%0,%1,%2,%3};"
        : "+f"(c[0]), "+f"(c[1]), "+f"(c[2]), "+f"(c[3])
        : "r"(a[0]), "r"(a[1]), "r"(a[2]), "r"(a[3]), "r"(b0), "r"(b1));
}

__device__ __forceinline__ void cp_async16(uint32_t dst, const void* src, int sz) {
    asm volatile("cp.async.cg.shared.global [%0], [%1], 16, %2;"
                 :: "r"(dst), "l"(src), "r"(sz) : "memory");
}

// SMEM layout for conv kernel (dynamic)
#define OFF_AH   0
#define OFF_AL   16384
#define OFF_B    32768
#define SMEM_BYTES 49152

// ================= kernels =================

// W[k][cin][cout] fp32 -> fused bf16 hi/lo B-fragments, column-permuted for red.v4.
// Also zeroes g_stats + tickets (block 0).
__global__ __launch_bounds__(256)
void prep_w_kernel(const float* __restrict__ W1, const float* __restrict__ W2, int K)
{
    const int k     = blockIdx.x;
    const int layer = blockIdx.y;
    const float* Wk = (layer ? W2 : W1) + (size_t)k * 4096;
    uint4* dst = (layer ? g_Wf2 : g_Wf1) + (size_t)k * 1024;

    if (blockIdx.x == 0 && blockIdx.y == 0) {
        if (threadIdx.x < 64)
            reinterpret_cast<float4*>(g_stats)[threadIdx.x] =
                make_float4(0.f, 0.f, 0.f, 0.f);
        if (threadIdx.x == 64) { g_cnt[0] = 0; g_cnt[1] = 0; }
    }

    for (int q = threadIdx.x; q < 1024; q += 256) {
        const int lane = q & 31;
        const int nt   = (q >> 5) & 7;
        const int ks   = q >> 8;
        const int l    = lane >> 2;
        const int n    = 16 * (nt >> 1) + 4 * (l >> 1) + 2 * (nt & 1) + (l & 1);
        uint32_t r[4];
        #pragma unroll
        for (int reg = 0; reg < 2; ++reg) {
            const int k0   = ks * 16 + (lane & 3) * 2 + reg * 8;
            const float v0 = Wk[k0 * 64 + n];
            const float v1 = Wk[(k0 + 1) * 64 + n];
            const __nv_bfloat16 h0 = __float2bfloat16(v0);
            const __nv_bfloat16 h1 = __float2bfloat16(v1);
            const __nv_bfloat16 l0 = __float2bfloat16(v0 - __bfloat162float(h0));
            const __nv_bfloat16 l1 = __float2bfloat16(v1 - __bfloat162float(h1));
            r[reg]     = (uint32_t)__bfloat16_as_ushort(h0)
                       | ((uint32_t)__bfloat16_as_ushort(h1) << 16);
            r[2 + reg] = (uint32_t)__bfloat16_as_ushort(l0)
                       | ((uint32_t)__bfloat16_as_ushort(l1) << 16);
        }
        dst[q] = make_uint4(r[0], r[1], r[2], r[3]);
    }
}

// fp32 rows -> bf16 hi/lo split (optional fused relu(bn) via sb).
// When z1 != nullptr also zero-fills buf rows (fused zero pass).
__global__ __launch_bounds__(256)
void prep_feat_kernel(const float* __restrict__ src, const float* __restrict__ sb,
                      float* __restrict__ z1, float* __restrict__ z2, int N)
{
    const int gid = blockIdx.x * blockDim.x + threadIdx.x;
    if (gid >= N * 8) return;
    const int row = gid >> 3;
    const int c0  = (gid & 7) * 8;

    const float4 v0 = reinterpret_cast<const float4*>(src + (size_t)row * 64 + c0)[0];
    const float4 v1 = reinterpret_cast<const float4*>(src + (size_t)row * 64 + c0)[1];
    float v[8] = {v0.x, v0.y, v0.z, v0.w, v1.x, v1.y, v1.z, v1.w};

    if (sb) {
        #pragma unroll
        for (int j = 0; j < 8; ++j)
            v[j] = fmaxf(fmaf(v[j], sb[c0 + j], sb[64 + c0 + j]), 0.f);
    }

    union { __nv_bfloat16 h[8]; uint4 u; } uh, ul;
    #pragma unroll
    for (int j = 0; j < 8; ++j) {
        const __nv_bfloat16 hi = __float2bfloat16(v[j]);
        uh.h[j] = hi;
        ul.h[j] = __float2bfloat16(v[j] - __bfloat162float(hi));
    }
    reinterpret_cast<uint4*>(g_fhi)[(size_t)row * 8 + (c0 >> 3)] = uh.u;
    reinterpret_cast<uint4*>(g_flo)[(size_t)row * 8 + (c0 >> 3)] = ul.u;

    if (z1) {
        const float4 z = make_float4(0.f, 0.f, 0.f, 0.f);
        const size_t f4 = (size_t)row * 16 + (c0 >> 2);
        reinterpret_cast<float4*>(z1)[f4]     = z;
        reinterpret_cast<float4*>(z1)[f4 + 1] = z;
        reinterpret_cast<float4*>(z2)[f4]     = z;
        reinterpret_cast<float4*>(z2)[f4 + 1] = z;
    }
}

// gather (cp.async, issued at entry) -> mma.sync bf16-split -> red.v4 scatter
// 8 warps arranged 4(row)x2(col); each warp: 32 rows x 32 cols.
// Map indices live in registers; B tile also filled via cp.async; single sync.
__global__ __launch_bounds__(256)
void conv_mma_kernel(const __nv_bfloat16* __restrict__ fhi,
                     const __nv_bfloat16* __restrict__ flo,
                     const uint4* __restrict__ Wf,
                     const int* __restrict__ in_maps,
                     const int* __restrict__ out_maps,
                     float* __restrict__ out,
                     int M)
{
    extern __shared__ char sm[];
    const int t    = threadIdx.x;
    const int lane = t & 31;
    const int w    = t >> 5;
    const int wr   = w >> 1;      // row group 0..3
    const int wc   = w & 1;       // col group 0..1
    const int k    = blockIdx.y;
    const int m0   = blockIdx.x * 128;

    const uint32_t ahb = smem_u32(sm + OFF_AH);
    const uint32_t alb = smem_u32(sm + OFF_AL);
    const uint32_t bsb = smem_u32(sm + OFF_B);

    // A gather via cp.async: 8 lanes per row, one 16B chunk each; indices by LDG.
    {
        const int c = t & 7;          // chunk 0..7
        const int g = t >> 3;         // row sub-index 0..31
        #pragma unroll
        for (int it = 0; it < 4; ++it) {
            const int row = it * 32 + g;
            const int m   = m0 + row;
            const int src = (m < M) ? in_maps[(size_t)k * M + m] : -1;
            const int sz  = (src >= 0) ? 16 : 0;
            const size_t base = (size_t)(src >= 0 ? src : 0) * 8 + c;
            const uint32_t d = (uint32_t)(row * 128 + ((c ^ (row & 7)) << 4));
            cp_async16(ahb + d, reinterpret_cast<const uint4*>(fhi) + base, sz);
            cp_async16(alb + d, reinterpret_cast<const uint4*>(flo) + base, sz);
        }
    }
    // B-fragment copy via cp.async (1024 uint4)
    {
        const uint4* s = Wf + (size_t)k * 1024;
        #pragma unroll
        for (int i = 0; i < 4; ++i)
            cp_async16(bsb + (t + i * 256) * 16, s + t + i * 256, 16);
    }
    asm volatile("cp.async.commit_group;" ::: "memory");
    asm volatile("cp.async.wait_group 0;" ::: "memory");
    __syncthreads();

    // MMA mainloop: warp covers rows [wr*32, wr*32+32), cols [wc*32, wc*32+32)
    float acc[2][4][4];
    #pragma unroll
    for (int rt = 0; rt < 2; ++rt)
        #pragma unroll
        for (int nl = 0; nl < 4; ++nl)
            #pragma unroll
            for (int j = 0; j < 4; ++j) acc[rt][nl][j] = 0.f;

    const uint4* B = reinterpret_cast<const uint4*>(sm + OFF_B);
    const int half = lane >> 4;

    #pragma unroll
    for (int ks = 0; ks < 4; ++ks) {
        uint32_t aH[2][4], aL[2][4];
        #pragma unroll
        for (int rt = 0; rt < 2; ++rt) {
            const int row   = wr * 32 + rt * 16 + (lane & 15);
            const int chunk = ks * 2 + half;
            const uint32_t off = row * 128 + ((chunk ^ (row & 7)) << 4);
            ldmatrix_x4(aH[rt], ahb + off);
            ldmatrix_x4(aL[rt], alb + off);
        }
        #pragma unroll
        for (int nl = 0; nl < 4; ++nl) {
            const int nt = wc * 4 + nl;
            const uint4 b = B[(ks * 8 + nt) * 32 + lane];
            #pragma unroll
            for (int rt = 0; rt < 2; ++rt) {
                mma16816(acc[rt][nl], aH[rt], b.x, b.y);
                mma16816(acc[rt][nl], aH[rt], b.z, b.w);
                mma16816(acc[rt][nl], aL[rt], b.x, b.y);
            }
        }
    }

    // scatter via red.v4; out indices by direct LDG (L2-hot broadcast)
    #pragma unroll
    for (int rt = 0; rt < 2; ++rt) {
        const int r0 = wr * 32 + rt * 16 + (lane >> 2);
        const int ma = m0 + r0;
        const int mb = ma + 8;
        const int o0 = (ma < M) ? out_maps[(size_t)k * M + ma] : -1;
        const int o1 = (mb < M) ? out_maps[(size_t)k * M + mb] : -1;
        const int cb = 4 * (lane & 3);
        #pragma unroll
        for (int p = 0; p < 2; ++p) {
            const int col = 16 * (wc * 2 + p) + cb;
            if (o0 >= 0) {
                asm volatile("red.global.add.v4.f32 [%0], {%1, %2, %3, %4};"
                    :: "l"(out + (size_t)o0 * 64 + col),
                       "f"(acc[rt][2*p][0]), "f"(acc[rt][2*p][1]),
                       "f"(acc[rt][2*p+1][0]), "f"(acc[rt][2*p+1][1]) : "memory");
            }
            if (o1 >= 0) {
                asm volatile("red.global.add.v4.f32 [%0], {%1, %2, %3, %4};"
                    :: "l"(out + (size_t)o1 * 64 + col),
                       "f"(acc[rt][2*p][2]), "f"(acc[rt][2*p][3]),
                       "f"(acc[rt][2*p+1][2]), "f"(acc[rt][2*p+1][3]) : "memory");
            }
        }
    }
}

// per-channel sum / sumsq (float4-vectorized) with fused finalize (last block)
__global__ __launch_bounds__(256)
void stats_kernel(const float* __restrict__ x, int N, float* __restrict__ sums,
                  const float* __restrict__ gamma, const float* __restrict__ beta,
                  float invN, float* __restrict__ sb, int cidx)
{
    const int t  = threadIdx.x;
    const int cg = t & 15;        // channel group (4 channels)
    const int rg = t >> 4;        // 16 row lanes per block
    float s0 = 0.f, s1 = 0.f, s2 = 0.f, s3 = 0.f;
    float q0 = 0.f, q1 = 0.f, q2 = 0.f, q3 = 0.f;
    const int stride = gridDim.x * 16;
    for (int r = blockIdx.x * 16 + rg; r < N; r += stride) {
        const float4 v = reinterpret_cast<const float4*>(x + (size_t)r * 64 + cg * 4)[0];
        s0 += v.x; s1 += v.y; s2 += v.z; s3 += v.w;
        q0 += v.x * v.x; q1 += v.y * v.y; q2 += v.z * v.z; q3 += v.w * v.w;
    }
    __shared__ float sh[256 * 8];
    __shared__ int last;
    float* my = sh + t * 8;
    my[0] = s0; my[1] = s1; my[2] = s2; my[3] = s3;
    my[4] = q0; my[5] = q1; my[6] = q2; my[7] = q3;
    __syncthreads();
    if (t < 64) {
        const int cgi = t >> 2;
        const int j   = t & 3;
        float S = 0.f, Q = 0.f;
        #pragma unroll
        for (int r = 0; r < 16; ++r) {
            const float* p = sh + (r * 16 + cgi) * 8 + j;
            S += p[0];
            Q += p[4];
        }
        atomicAdd(&sums[t],      S);
        atomicAdd(&sums[64 + t], Q);
    }
    // last block finalizes scale/shift
    __syncthreads();
    if (t == 0) {
        __threadfence();
        last = (atomicAdd(&g_cnt[cidx], 1u) == gridDim.x - 1) ? 1 : 0;
    }
    __syncthreads();
    if (last && t < 64) {
        const float mean = sums[t] * invN;
        const float var  = fmaxf(sums[64 + t] * invN - mean * mean, 0.f);
        const float s    = gamma[t] * rsqrtf(var + EPSV);
        sb[t]      = s;
        sb[64 + t] = beta[t] - mean * s;
    }
}

__global__ __launch_bounds__(256)
void final_kernel(const float* __restrict__ conv2, const float* __restrict__ sb2,
                  const float* __restrict__ feat, float* __restrict__ out, int n4)
{
    int i = blockIdx.x * blockDim.x + threadIdx.x;
    for (int j = i; j < n4; j += gridDim.x * blockDim.x) {
        const float4 v = reinterpret_cast<const float4*>(conv2)[j];
        const float4 f = reinterpret_cast<const float4*>(feat)[j];
        const int c0 = (j & 15) * 4;
        float4 r;
        r.x = fmaxf(fmaf(v.x, sb2[c0 + 0], sb2[64 + c0 + 0]) + f.x, 0.f);
        r.y = fmaxf(fmaf(v.y, sb2[c0 + 1], sb2[64 + c0 + 1]) + f.y, 0.f);
        r.z = fmaxf(fmaf(v.z, sb2[c0 + 2], sb2[64 + c0 + 2]) + f.z, 0.f);
        r.w = fmaxf(fmaf(v.w, sb2[c0 + 3], sb2[64 + c0 + 3]) + f.w, 0.f);
        reinterpret_cast<float4*>(out)[j] = r;
    }
}

// ================= launcher =================
extern "C" void kernel_launch(void* const* d_in, const int* in_sizes, int n_in,
                              void* d_out, int out_size)
{
    const float* features = (const float*)d_in[0];
    const float* W1       = (const float*)d_in[1];
    const float* gamma1   = (const float*)d_in[2];
    const float* beta1    = (const float*)d_in[3];
    const float* W2       = (const float*)d_in[4];
    const float* gamma2   = (const float*)d_in[5];
    const float* beta2    = (const float*)d_in[6];
    const int*   in_maps  = (const int*)d_in[7];
    const int*   out_maps = (const int*)d_in[8];
    float*       out      = (float*)d_out;

    const int N = in_sizes[0] / CH;
    const int K = in_sizes[1] / (CH * CH);
    const int M = in_sizes[7] / K;

    float* buf1;  cudaGetSymbolAddress((void**)&buf1,  g_buf1);
    float* buf2;  cudaGetSymbolAddress((void**)&buf2,  g_buf2);
    float* stats; cudaGetSymbolAddress((void**)&stats, g_stats);
    float* sb;    cudaGetSymbolAddress((void**)&sb,    g_sb);
    __nv_bfloat16 *fhi, *flo;
    cudaGetSymbolAddress((void**)&fhi, g_fhi);
    cudaGetSymbolAddress((void**)&flo, g_flo);
    uint4 *wf1, *wf2;
    cudaGetSymbolAddress((void**)&wf1, g_Wf1);
    cudaGetSymbolAddress((void**)&wf2, g_Wf2);

    cudaFuncSetAttribute(conv_mma_kernel,
                         cudaFuncAttributeMaxDynamicSharedMemorySize, SMEM_BYTES);

    const int total4 = N * (CH / 4);
    const float invN = 1.0f / (float)N;
    const dim3 convGrid((M + 127) / 128, K);
    const int pfBlocks = (N * 8 + 255) / 256;

    prep_w_kernel<<<dim3(K, 2), 256>>>(W1, W2, K);

    // conv1 (prep also zeroes buf1/buf2)
    prep_feat_kernel<<<pfBlocks, 256>>>(features, nullptr, buf1, buf2, N);
    conv_mma_kernel<<<convGrid, 256, SMEM_BYTES>>>(fhi, flo, wf1,
                                                   in_maps, out_maps, buf1, M);
    stats_kernel<<<512, 256>>>(buf1, N, stats, gamma1, beta1, invN, sb, 0);

    // conv2 (BN1+ReLU fused into split pass)
    prep_feat_kernel<<<pfBlocks, 256>>>(buf1, sb, nullptr, nullptr, N);
    conv_mma_kernel<<<convGrid, 256, SMEM_BYTES>>>(fhi, flo, wf2,
                                                   in_maps, out_maps, buf2, M);
    stats_kernel<<<512, 256>>>(buf2, N, stats + 128, gamma2, beta2, invN,
                               sb + 128, 1);

    final_kernel<<<1024, 256>>>(buf2, sb + 128, features, out, total4);
}

// round 11
// speedup vs baseline: 1.7929x; 1.0408x over previous
#include <cuda_runtime.h>
#include <cuda_bf16.h>
#include <cstdint>

#define CH    64
#define EPSV  1e-5f
#define MAXN  100000
#define MAXK  27

// ================= scratch (__device__ globals, alloc-free) =================
__device__ float g_buf1[MAXN * CH];      // conv1 raw output (fp32)
__device__ float g_buf2[MAXN * CH];      // conv2 raw output (fp32)
__device__ float g_stats[256];           // [sum1, sumsq1, sum2, sumsq2]
__device__ float g_sb[256];              // [scale1, shift1, scale2, shift2]
__device__ unsigned int g_cnt[2];        // stats completion tickets
__device__ __align__(16) __nv_bfloat16 g_fhi[MAXN * CH];
__device__ __align__(16) __nv_bfloat16 g_flo[MAXN * CH];
// W pre-packed in fused mma B-fragment order: uint4{bh_reg0, bh_reg1, bl_reg0, bl_reg1}
__device__ __align__(16) uint4 g_Wf1[MAXK * 1024];
__device__ __align__(16) uint4 g_Wf2[MAXK * 1024];

// ================= helpers =================
__device__ __forceinline__ uint32_t smem_u32(const void* p) {
    uint32_t a;
    asm("{ .reg .u64 t; cvta.to.shared.u64 t, %1; cvt.u32.u64 %0, t; }" : "=r"(a) : "l"(p));
    return a;
}

__device__ __forceinline__ void ldmatrix_x4(uint32_t* r, uint32_t addr) {
    asm volatile("ldmatrix.sync.aligned.m8n8.x4.shared.b16 {%0,%1,%2,%3}, [%4];"
                 : "=r"(r[0]), "=r"(r[1]), "=r"(r[2]), "=r"(r[3]) : "r"(addr));
}

__device__ __forceinline__ void mma16816(float* c, const uint32_t* a,
                                         uint32_t b0, uint32_t b1) {
    asm volatile(
        "mma.sync.aligned.m16n8k16.row.col.f32.bf16.bf16.f32 "
        "{%0,%1,%2,%3}, {%4,%5,%6,%7}, {%8,%9}, {%0,%1,%2,%3};"
        : "+f"(c[0]), "+f"(c[1]), "+f"(c[2]), "+f"(c[3])
        : "r"(a[0]), "r"(a[1]), "r"(a[2]), "r"(a[3]), "r"(b0), "r"(b1));
}

__device__ __forceinline__ void cp_async16(uint32_t dst, const void* src, int sz) {
    asm volatile("cp.async.cg.shared.global [%0], [%1], 16, %2;"
                 :: "r"(dst), "l"(src), "r"(sz) : "memory");
}

// SMEM layout for conv kernel (dynamic)
#define OFF_AH   0
#define OFF_AL   16384
#define OFF_B    32768
#define SMEM_BYTES 49152

// ================= kernels =================

// W[k][cin][cout] fp32 -> fused bf16 hi/lo B-fragments, column-permuted for red.v4.
// Also zeroes g_stats + tickets (block 0).
__global__ __launch_bounds__(256)
void prep_w_kernel(const float* __restrict__ W1, const float* __restrict__ W2, int K)
{
    const int k     = blockIdx.x;
    const int layer = blockIdx.y;
    const float* Wk = (layer ? W2 : W1) + (size_t)k * 4096;
    uint4* dst = (layer ? g_Wf2 : g_Wf1) + (size_t)k * 1024;

    if (blockIdx.x == 0 && blockIdx.y == 0) {
        if (threadIdx.x < 64)
            reinterpret_cast<float4*>(g_stats)[threadIdx.x] =
                make_float4(0.f, 0.f, 0.f, 0.f);
        if (threadIdx.x == 64) { g_cnt[0] = 0; g_cnt[1] = 0; }
    }

    for (int q = threadIdx.x; q < 1024; q += 256) {
        const int lane = q & 31;
        const int nt   = (q >> 5) & 7;
        const int ks   = q >> 8;
        const int l    = lane >> 2;
        const int n    = 16 * (nt >> 1) + 4 * (l >> 1) + 2 * (nt & 1) + (l & 1);
        uint32_t r[4];
        #pragma unroll
        for (int reg = 0; reg < 2; ++reg) {
            const int k0   = ks * 16 + (lane & 3) * 2 + reg * 8;
            const float v0 = Wk[k0 * 64 + n];
            const float v1 = Wk[(k0 + 1) * 64 + n];
            const __nv_bfloat16 h0 = __float2bfloat16(v0);
            const __nv_bfloat16 h1 = __float2bfloat16(v1);
            const __nv_bfloat16 l0 = __float2bfloat16(v0 - __bfloat162float(h0));
            const __nv_bfloat16 l1 = __float2bfloat16(v1 - __bfloat162float(h1));
            r[reg]     = (uint32_t)__bfloat16_as_ushort(h0)
                       | ((uint32_t)__bfloat16_as_ushort(h1) << 16);
            r[2 + reg] = (uint32_t)__bfloat16_as_ushort(l0)
                       | ((uint32_t)__bfloat16_as_ushort(l1) << 16);
        }
        dst[q] = make_uint4(r[0], r[1], r[2], r[3]);
    }
}

// fp32 rows -> bf16 hi/lo split (optional fused relu(bn) via sb).
// When z1 != nullptr also zero-fills buf rows (fused zero pass).
__global__ __launch_bounds__(256)
void prep_feat_kernel(const float* __restrict__ src, const float* __restrict__ sb,
                      float* __restrict__ z1, float* __restrict__ z2, int N)
{
    const int gid = blockIdx.x * blockDim.x + threadIdx.x;
    if (gid >= N * 8) return;
    const int row = gid >> 3;
    const int c0  = (gid & 7) * 8;

    const float4 v0 = reinterpret_cast<const float4*>(src + (size_t)row * 64 + c0)[0];
    const float4 v1 = reinterpret_cast<const float4*>(src + (size_t)row * 64 + c0)[1];
    float v[8] = {v0.x, v0.y, v0.z, v0.w, v1.x, v1.y, v1.z, v1.w};

    if (sb) {
        #pragma unroll
        for (int j = 0; j < 8; ++j)
            v[j] = fmaxf(fmaf(v[j], sb[c0 + j], sb[64 + c0 + j]), 0.f);
    }

    union { __nv_bfloat16 h[8]; uint4 u; } uh, ul;
    #pragma unroll
    for (int j = 0; j < 8; ++j) {
        const __nv_bfloat16 hi = __float2bfloat16(v[j]);
        uh.h[j] = hi;
        ul.h[j] = __float2bfloat16(v[j] - __bfloat162float(hi));
    }
    reinterpret_cast<uint4*>(g_fhi)[(size_t)row * 8 + (c0 >> 3)] = uh.u;
    reinterpret_cast<uint4*>(g_flo)[(size_t)row * 8 + (c0 >> 3)] = ul.u;

    if (z1) {
        const float4 z = make_float4(0.f, 0.f, 0.f, 0.f);
        const size_t f4 = (size_t)row * 16 + (c0 >> 2);
        reinterpret_cast<float4*>(z1)[f4]     = z;
        reinterpret_cast<float4*>(z1)[f4 + 1] = z;
        reinterpret_cast<float4*>(z2)[f4]     = z;
        reinterpret_cast<float4*>(z2)[f4 + 1] = z;
    }
}

// gather (cp.async, issued at entry) -> mma.sync bf16-split -> red.v4 scatter
// 8 warps arranged 4(row)x2(col); each warp: 32 rows x 32 cols.
// All scratch offsets computed in uint32 (register slimming for 4 CTAs/SM).
__global__ __launch_bounds__(256)
void conv_mma_kernel(const __nv_bfloat16* __restrict__ fhi,
                     const __nv_bfloat16* __restrict__ flo,
                     const uint4* __restrict__ Wf,
                     const int* __restrict__ in_maps,
                     const int* __restrict__ out_maps,
                     float* __restrict__ out,
                     int M)
{
    extern __shared__ char sm[];
    const int t    = threadIdx.x;
    const int lane = t & 31;
    const int w    = t >> 5;
    const int wr   = w >> 1;      // row group 0..3
    const int wc   = w & 1;       // col group 0..1
    const int k    = blockIdx.y;
    const int m0   = blockIdx.x * 128;
    const int mrem = M - m0;      // rows valid in this tile (may exceed 128)

    const uint32_t ahb = smem_u32(sm + OFF_AH);
    const uint32_t alb = smem_u32(sm + OFF_AL);
    const uint32_t bsb = smem_u32(sm + OFF_B);

    const int* im = in_maps  + (size_t)k * M + m0;
    const int* om = out_maps + (size_t)k * M + m0;

    // A gather via cp.async: 8 lanes per row, one 16B chunk each.
    {
        const int c = t & 7;          // chunk 0..7
        const int g = t >> 3;         // row sub-index 0..31
        #pragma unroll
        for (int it = 0; it < 4; ++it) {
            const int row = it * 32 + g;
            const int src = (row < mrem) ? im[row] : -1;
            const int sz  = (src >= 0) ? 16 : 0;
            const uint32_t base = (uint32_t)(src >= 0 ? src : 0) * 8u + (uint32_t)c;
            const uint32_t d = (uint32_t)(row * 128 + ((c ^ (row & 7)) << 4));
            cp_async16(ahb + d, reinterpret_cast<const uint4*>(fhi) + base, sz);
            cp_async16(alb + d, reinterpret_cast<const uint4*>(flo) + base, sz);
        }
    }
    // B-fragment copy via cp.async (1024 uint4)
    {
        const uint4* s = Wf + (size_t)k * 1024;
        #pragma unroll
        for (int i = 0; i < 4; ++i)
            cp_async16(bsb + (uint32_t)(t + i * 256) * 16u, s + t + i * 256, 16);
    }
    asm volatile("cp.async.commit_group;" ::: "memory");
    asm volatile("cp.async.wait_group 0;" ::: "memory");
    __syncthreads();

    // MMA mainloop: warp covers rows [wr*32, wr*32+32), cols [wc*32, wc*32+32)
    float acc[2][4][4];
    #pragma unroll
    for (int rt = 0; rt < 2; ++rt)
        #pragma unroll
        for (int nl = 0; nl < 4; ++nl)
            #pragma unroll
            for (int j = 0; j < 4; ++j) acc[rt][nl][j] = 0.f;

    const uint4* B = reinterpret_cast<const uint4*>(sm + OFF_B);
    const int half = lane >> 4;

    #pragma unroll
    for (int ks = 0; ks < 4; ++ks) {
        uint32_t aH[2][4], aL[2][4];
        #pragma unroll
        for (int rt = 0; rt < 2; ++rt) {
            const int row   = wr * 32 + rt * 16 + (lane & 15);
            const int chunk = ks * 2 + half;
            const uint32_t off = (uint32_t)(row * 128 + ((chunk ^ (row & 7)) << 4));
            ldmatrix_x4(aH[rt], ahb + off);
            ldmatrix_x4(aL[rt], alb + off);
        }
        #pragma unroll
        for (int nl = 0; nl < 4; ++nl) {
            const int nt = wc * 4 + nl;
            const uint4 b = B[(ks * 8 + nt) * 32 + lane];
            #pragma unroll
            for (int rt = 0; rt < 2; ++rt) {
                mma16816(acc[rt][nl], aH[rt], b.x, b.y);
                mma16816(acc[rt][nl], aH[rt], b.z, b.w);
                mma16816(acc[rt][nl], aL[rt], b.x, b.y);
            }
        }
    }

    // scatter via red.v4; out indices by direct LDG, 32-bit offset math
    #pragma unroll
    for (int rt = 0; rt < 2; ++rt) {
        const int r0 = wr * 32 + rt * 16 + (lane >> 2);
        const int o0 = (r0     < mrem) ? om[r0]     : -1;
        const int o1 = (r0 + 8 < mrem) ? om[r0 + 8] : -1;
        const uint32_t cb = 4u * (uint32_t)(lane & 3);
        #pragma unroll
        for (int p = 0; p < 2; ++p) {
            const uint32_t col = 16u * (uint32_t)(wc * 2 + p) + cb;
            if (o0 >= 0) {
                asm volatile("red.global.add.v4.f32 [%0], {%1, %2, %3, %4};"
                    :: "l"(out + (uint32_t)o0 * 64u + col),
                       "f"(acc[rt][2*p][0]), "f"(acc[rt][2*p][1]),
                       "f"(acc[rt][2*p+1][0]), "f"(acc[rt][2*p+1][1]) : "memory");
            }
            if (o1 >= 0) {
                asm volatile("red.global.add.v4.f32 [%0], {%1, %2, %3, %4};"
                    :: "l"(out + (uint32_t)o1 * 64u + col),
                       "f"(acc[rt][2*p][2]), "f"(acc[rt][2*p][3]),
                       "f"(acc[rt][2*p+1][2]), "f"(acc[rt][2*p+1][3]) : "memory");
            }
        }
    }
}

// per-channel sum / sumsq (float4-vectorized) with fused finalize (last block)
__global__ __launch_bounds__(256)
void stats_kernel(const float* __restrict__ x, int N, float* __restrict__ sums,
                  const float* __restrict__ gamma, const float* __restrict__ beta,
                  float invN, float* __restrict__ sb, int cidx)
{
    const int t  = threadIdx.x;
    const int cg = t & 15;        // channel group (4 channels)
    const int rg = t >> 4;        // 16 row lanes per block
    float s0 = 0.f, s1 = 0.f, s2 = 0.f, s3 = 0.f;
    float q0 = 0.f, q1 = 0.f, q2 = 0.f, q3 = 0.f;
    const int stride = gridDim.x * 16;
    for (int r = blockIdx.x * 16 + rg; r < N; r += stride) {
        const float4 v = reinterpret_cast<const float4*>(x + (size_t)r * 64 + cg * 4)[0];
        s0 += v.x; s1 += v.y; s2 += v.z; s3 += v.w;
        q0 += v.x * v.x; q1 += v.y * v.y; q2 += v.z * v.z; q3 += v.w * v.w;
    }
    __shared__ float sh[256 * 8];
    __shared__ int last;
    float* my = sh + t * 8;
    my[0] = s0; my[1] = s1; my[2] = s2; my[3] = s3;
    my[4] = q0; my[5] = q1; my[6] = q2; my[7] = q3;
    __syncthreads();
    if (t < 64) {
        const int cgi = t >> 2;
        const int j   = t & 3;
        float S = 0.f, Q = 0.f;
        #pragma unroll
        for (int r = 0; r < 16; ++r) {
            const float* p = sh + (r * 16 + cgi) * 8 + j;
            S += p[0];
            Q += p[4];
        }
        atomicAdd(&sums[t],      S);
        atomicAdd(&sums[64 + t], Q);
    }
    // last block finalizes scale/shift
    __syncthreads();
    if (t == 0) {
        __threadfence();
        last = (atomicAdd(&g_cnt[cidx], 1u) == gridDim.x - 1) ? 1 : 0;
    }
    __syncthreads();
    if (last && t < 64) {
        const float mean = sums[t] * invN;
        const float var  = fmaxf(sums[64 + t] * invN - mean * mean, 0.f);
        const float s    = gamma[t] * rsqrtf(var + EPSV);
        sb[t]      = s;
        sb[64 + t] = beta[t] - mean * s;
    }
}

__global__ __launch_bounds__(256)
void final_kernel(const float* __restrict__ conv2, const float* __restrict__ sb2,
                  const float* __restrict__ feat, float* __restrict__ out, int n4)
{
    int i = blockIdx.x * blockDim.x + threadIdx.x;
    for (int j = i; j < n4; j += gridDim.x * blockDim.x) {
        const float4 v = reinterpret_cast<const float4*>(conv2)[j];
        const float4 f = reinterpret_cast<const float4*>(feat)[j];
        const int c0 = (j & 15) * 4;
        float4 r;
        r.x = fmaxf(fmaf(v.x, sb2[c0 + 0], sb2[64 + c0 + 0]) + f.x, 0.f);
        r.y = fmaxf(fmaf(v.y, sb2[c0 + 1], sb2[64 + c0 + 1]) + f.y, 0.f);
        r.z = fmaxf(fmaf(v.z, sb2[c0 + 2], sb2[64 + c0 + 2]) + f.z, 0.f);
        r.w = fmaxf(fmaf(v.w, sb2[c0 + 3], sb2[64 + c0 + 3]) + f.w, 0.f);
        reinterpret_cast<float4*>(out)[j] = r;
    }
}

// ================= launcher =================
extern "C" void kernel_launch(void* const* d_in, const int* in_sizes, int n_in,
                              void* d_out, int out_size)
{
    const float* features = (const float*)d_in[0];
    const float* W1       = (const float*)d_in[1];
    const float* gamma1   = (const float*)d_in[2];
    const float* beta1    = (const float*)d_in[3];
    const float* W2       = (const float*)d_in[4];
    const float* gamma2   = (const float*)d_in[5];
    const float* beta2    = (const float*)d_in[6];
    const int*   in_maps  = (const int*)d_in[7];
    const int*   out_maps = (const int*)d_in[8];
    float*       out      = (float*)d_out;

    const int N = in_sizes[0] / CH;
    const int K = in_sizes[1] / (CH * CH);
    const int M = in_sizes[7] / K;

    float* buf1;  cudaGetSymbolAddress((void**)&buf1,  g_buf1);
    float* buf2;  cudaGetSymbolAddress((void**)&buf2,  g_buf2);
    float* stats; cudaGetSymbolAddress((void**)&stats, g_stats);
    float* sb;    cudaGetSymbolAddress((void**)&sb,    g_sb);
    __nv_bfloat16 *fhi, *flo;
    cudaGetSymbolAddress((void**)&fhi, g_fhi);
    cudaGetSymbolAddress((void**)&flo, g_flo);
    uint4 *wf1, *wf2;
    cudaGetSymbolAddress((void**)&wf1, g_Wf1);
    cudaGetSymbolAddress((void**)&wf2, g_Wf2);

    cudaFuncSetAttribute(conv_mma_kernel,
                         cudaFuncAttributeMaxDynamicSharedMemorySize, SMEM_BYTES);

    const int total4 = N * (CH / 4);
    const float invN = 1.0f / (float)N;
    const dim3 convGrid((M + 127) / 128, K);
    const int pfBlocks = (N * 8 + 255) / 256;

    prep_w_kernel<<<dim3(K, 2), 256>>>(W1, W2, K);

    // conv1 (prep also zeroes buf1/buf2)
    prep_feat_kernel<<<pfBlocks, 256>>>(features, nullptr, buf1, buf2, N);
    conv_mma_kernel<<<convGrid, 256, SMEM_BYTES>>>(fhi, flo, wf1,
                                                   in_maps, out_maps, buf1, M);
    stats_kernel<<<512, 256>>>(buf1, N, stats, gamma1, beta1, invN, sb, 0);

    // conv2 (BN1+ReLU fused into split pass)
    prep_feat_kernel<<<pfBlocks, 256>>>(buf1, sb, nullptr, nullptr, N);
    conv_mma_kernel<<<convGrid, 256, SMEM_BYTES>>>(fhi, flo, wf2,
                                                   in_maps, out_maps, buf2, M);
    stats_kernel<<<512, 256>>>(buf2, N, stats + 128, gamma2, beta2, invN,
                               sb + 128, 1);

    final_kernel<<<1024, 256>>>(buf2, sb + 128, features, out, total4);
}

// round 12
// speedup vs baseline: 1.9023x; 1.0610x over previous
#include <cuda_runtime.h>
#include <cuda_bf16.h>
#include <cstdint>

#define CH    64
#define EPSV  1e-5f
#define MAXN  100000
#define MAXK  27

// ================= scratch (__device__ globals, alloc-free) =================
__device__ float g_buf1[MAXN * CH];      // conv1 raw output (fp32)
__device__ float g_buf2[MAXN * CH];      // conv2 raw output (fp32)
__device__ float g_stats[256];           // [sum1, sumsq1, sum2, sumsq2]
__device__ float g_sb[256];              // [scale1, shift1, scale2, shift2]
__device__ unsigned int g_cnt[2];        // stats completion tickets
__device__ __align__(16) __nv_bfloat16 g_fhi[MAXN * CH];
__device__ __align__(16) __nv_bfloat16 g_flo[MAXN * CH];
// W pre-packed in fused mma B-fragment order: uint4{bh_reg0, bh_reg1, bl_reg0, bl_reg1}
__device__ __align__(16) uint4 g_Wf1[MAXK * 1024];
__device__ __align__(16) uint4 g_Wf2[MAXK * 1024];

// ================= helpers =================
__device__ __forceinline__ uint32_t smem_u32(const void* p) {
    uint32_t a;
    asm("{ .reg .u64 t; cvta.to.shared.u64 t, %1; cvt.u32.u64 %0, t; }" : "=r"(a) : "l"(p));
    return a;
}

__device__ __forceinline__ void ldmatrix_x4(uint32_t* r, uint32_t addr) {
    asm volatile("ldmatrix.sync.aligned.m8n8.x4.shared.b16 {%0,%1,%2,%3}, [%4];"
                 : "=r"(r[0]), "=r"(r[1]), "=r"(r[2]), "=r"(r[3]) : "r"(addr));
}

__device__ __forceinline__ void mma16816(float* c, const uint32_t* a,
                                         uint32_t b0, uint32_t b1) {
    asm volatile(
        "mma.sync.aligned.m16n8k16.row.col.f32.bf16.bf16.f32 "
        "{%0,%1,%2,%3}, {%4,%5,%6,%7}, {%8,%9}, {%0,%1,%2,%3};"
        : "+f"(c[0]), "+f"(c[1]), "+f"(c[2]), "+f"(c[3])
        : "r"(a[0]), "r"(a[1]), "r"(a[2]), "r"(a[3]), "r"(b0), "r"(b1));
}

__device__ __forceinline__ void cp_async16(uint32_t dst, const void* src, int sz) {
    asm volatile("cp.async.cg.shared.global [%0], [%1], 16, %2;"
                 :: "r"(dst), "l"(src), "r"(sz) : "memory");
}

// SMEM layout for conv kernel (dynamic)
#define OFF_AH   0
#define OFF_AL   16384
#define OFF_B    32768
#define SMEM_BYTES 49152

// ================= kernels =================

// W[k][cin][cout] fp32 -> fused bf16 hi/lo B-fragments, column-permuted for red.v4.
// Also zeroes g_stats + tickets (block 0).
__global__ __launch_bounds__(256)
void prep_w_kernel(const float* __restrict__ W1, const float* __restrict__ W2, int K)
{
    const int k     = blockIdx.x;
    const int layer = blockIdx.y;
    const float* Wk = (layer ? W2 : W1) + (size_t)k * 4096;
    uint4* dst = (layer ? g_Wf2 : g_Wf1) + (size_t)k * 1024;

    if (blockIdx.x == 0 && blockIdx.y == 0) {
        if (threadIdx.x < 64)
            reinterpret_cast<float4*>(g_stats)[threadIdx.x] =
                make_float4(0.f, 0.f, 0.f, 0.f);
        if (threadIdx.x == 64) { g_cnt[0] = 0; g_cnt[1] = 0; }
    }

    for (int q = threadIdx.x; q < 1024; q += 256) {
        const int lane = q & 31;
        const int nt   = (q >> 5) & 7;
        const int ks   = q >> 8;
        const int l    = lane >> 2;
        const int n    = 16 * (nt >> 1) + 4 * (l >> 1) + 2 * (nt & 1) + (l & 1);
        uint32_t r[4];
        #pragma unroll
        for (int reg = 0; reg < 2; ++reg) {
            const int k0   = ks * 16 + (lane & 3) * 2 + reg * 8;
            const float v0 = Wk[k0 * 64 + n];
            const float v1 = Wk[(k0 + 1) * 64 + n];
            const __nv_bfloat16 h0 = __float2bfloat16(v0);
            const __nv_bfloat16 h1 = __float2bfloat16(v1);
            const __nv_bfloat16 l0 = __float2bfloat16(v0 - __bfloat162float(h0));
            const __nv_bfloat16 l1 = __float2bfloat16(v1 - __bfloat162float(h1));
            r[reg]     = (uint32_t)__bfloat16_as_ushort(h0)
                       | ((uint32_t)__bfloat16_as_ushort(h1) << 16);
            r[2 + reg] = (uint32_t)__bfloat16_as_ushort(l0)
                       | ((uint32_t)__bfloat16_as_ushort(l1) << 16);
        }
        dst[q] = make_uint4(r[0], r[1], r[2], r[3]);
    }
}

// fp32 rows -> bf16 hi/lo split (optional fused relu(bn) via sb).
// When z1 != nullptr also zero-fills buf rows (fused zero pass).
__global__ __launch_bounds__(256)
void prep_feat_kernel(const float* __restrict__ src, const float* __restrict__ sb,
                      float* __restrict__ z1, float* __restrict__ z2, int N)
{
    const int gid = blockIdx.x * blockDim.x + threadIdx.x;
    if (gid >= N * 8) return;
    const int row = gid >> 3;
    const int c0  = (gid & 7) * 8;

    const float4 v0 = reinterpret_cast<const float4*>(src + (size_t)row * 64 + c0)[0];
    const float4 v1 = reinterpret_cast<const float4*>(src + (size_t)row * 64 + c0)[1];
    float v[8] = {v0.x, v0.y, v0.z, v0.w, v1.x, v1.y, v1.z, v1.w};

    if (sb) {
        #pragma unroll
        for (int j = 0; j < 8; ++j)
            v[j] = fmaxf(fmaf(v[j], sb[c0 + j], sb[64 + c0 + j]), 0.f);
    }

    union { __nv_bfloat16 h[8]; uint4 u; } uh, ul;
    #pragma unroll
    for (int j = 0; j < 8; ++j) {
        const __nv_bfloat16 hi = __float2bfloat16(v[j]);
        uh.h[j] = hi;
        ul.h[j] = __float2bfloat16(v[j] - __bfloat162float(hi));
    }
    reinterpret_cast<uint4*>(g_fhi)[(size_t)row * 8 + (c0 >> 3)] = uh.u;
    reinterpret_cast<uint4*>(g_flo)[(size_t)row * 8 + (c0 >> 3)] = ul.u;

    if (z1) {
        const float4 z = make_float4(0.f, 0.f, 0.f, 0.f);
        const size_t f4 = (size_t)row * 16 + (c0 >> 2);
        reinterpret_cast<float4*>(z1)[f4]     = z;
        reinterpret_cast<float4*>(z1)[f4 + 1] = z;
        reinterpret_cast<float4*>(z2)[f4]     = z;
        reinterpret_cast<float4*>(z2)[f4 + 1] = z;
    }
}

// gather (cp.async, issued at entry) -> mma.sync bf16-split -> red.v4 scatter
// 8 warps arranged 4(row)x2(col); each warp: 32 rows x 32 cols.
// 4 CTAs/SM requested; natural regs ~66 -> ptxas remat should reach 64 cleanly.
__global__ __launch_bounds__(256, 4)
void conv_mma_kernel(const __nv_bfloat16* __restrict__ fhi,
                     const __nv_bfloat16* __restrict__ flo,
                     const uint4* __restrict__ Wf,
                     const int* __restrict__ in_maps,
                     const int* __restrict__ out_maps,
                     float* __restrict__ out,
                     int M)
{
    extern __shared__ char sm[];
    const int t    = threadIdx.x;
    const int lane = t & 31;
    const int w    = t >> 5;
    const int wr   = w >> 1;      // row group 0..3
    const int wc   = w & 1;       // col group 0..1
    const int k    = blockIdx.y;
    const int m0   = blockIdx.x * 128;
    const int mrem = M - m0;

    const uint32_t ahb = smem_u32(sm + OFF_AH);
    const uint32_t alb = smem_u32(sm + OFF_AL);
    const uint32_t bsb = smem_u32(sm + OFF_B);

    const int* im = in_maps  + (size_t)k * M + m0;
    const int* om = out_maps + (size_t)k * M + m0;

    // A gather via cp.async: 8 lanes per row, one 16B chunk each.
    {
        const int c = t & 7;          // chunk 0..7
        const int g = t >> 3;         // row sub-index 0..31
        #pragma unroll
        for (int it = 0; it < 4; ++it) {
            const int row = it * 32 + g;
            const int src = (row < mrem) ? im[row] : -1;
            const int sz  = (src >= 0) ? 16 : 0;
            const uint32_t base = (uint32_t)(src >= 0 ? src : 0) * 8u + (uint32_t)c;
            const uint32_t d = (uint32_t)(row * 128 + ((c ^ (row & 7)) << 4));
            cp_async16(ahb + d, reinterpret_cast<const uint4*>(fhi) + base, sz);
            cp_async16(alb + d, reinterpret_cast<const uint4*>(flo) + base, sz);
        }
    }
    // B-fragment copy via cp.async (1024 uint4)
    {
        const uint4* s = Wf + (size_t)k * 1024;
        #pragma unroll
        for (int i = 0; i < 4; ++i)
            cp_async16(bsb + (uint32_t)(t + i * 256) * 16u, s + t + i * 256, 16);
    }
    asm volatile("cp.async.commit_group;" ::: "memory");
    asm volatile("cp.async.wait_group 0;" ::: "memory");
    __syncthreads();

    // MMA mainloop: warp covers rows [wr*32, wr*32+32), cols [wc*32, wc*32+32)
    float acc[2][4][4];
    #pragma unroll
    for (int rt = 0; rt < 2; ++rt)
        #pragma unroll
        for (int nl = 0; nl < 4; ++nl)
            #pragma unroll
            for (int j = 0; j < 4; ++j) acc[rt][nl][j] = 0.f;

    const uint4* B = reinterpret_cast<const uint4*>(sm + OFF_B);
    const int half = lane >> 4;

    // hoisted LDSM row bases (constant across ks)
    uint32_t arow[2], sw[2];
    #pragma unroll
    for (int rt = 0; rt < 2; ++rt) {
        const int row = wr * 32 + rt * 16 + (lane & 15);
        arow[rt] = (uint32_t)(row * 128);
        sw[rt]   = (uint32_t)(row & 7);
    }

    #pragma unroll
    for (int ks = 0; ks < 4; ++ks) {
        uint32_t aH[2][4], aL[2][4];
        #pragma unroll
        for (int rt = 0; rt < 2; ++rt) {
            const uint32_t off = arow[rt]
                + ((((uint32_t)(ks * 2 + half)) ^ sw[rt]) << 4);
            ldmatrix_x4(aH[rt], ahb + off);
            ldmatrix_x4(aL[rt], alb + off);
        }
        #pragma unroll
        for (int nl = 0; nl < 4; ++nl) {
            const int nt = wc * 4 + nl;
            const uint4 b = B[(ks * 8 + nt) * 32 + lane];
            #pragma unroll
            for (int rt = 0; rt < 2; ++rt) {
                mma16816(acc[rt][nl], aH[rt], b.x, b.y);
                mma16816(acc[rt][nl], aH[rt], b.z, b.w);
                mma16816(acc[rt][nl], aL[rt], b.x, b.y);
            }
        }
    }

    // scatter via red.v4; out indices by direct LDG, 32-bit offset math
    #pragma unroll
    for (int rt = 0; rt < 2; ++rt) {
        const int r0 = wr * 32 + rt * 16 + (lane >> 2);
        const int o0 = (r0     < mrem) ? om[r0]     : -1;
        const int o1 = (r0 + 8 < mrem) ? om[r0 + 8] : -1;
        const uint32_t cb = 4u * (uint32_t)(lane & 3);
        #pragma unroll
        for (int p = 0; p < 2; ++p) {
            const uint32_t col = 16u * (uint32_t)(wc * 2 + p) + cb;
            if (o0 >= 0) {
                asm volatile("red.global.add.v4.f32 [%0], {%1, %2, %3, %4};"
                    :: "l"(out + (uint32_t)o0 * 64u + col),
                       "f"(acc[rt][2*p][0]), "f"(acc[rt][2*p][1]),
                       "f"(acc[rt][2*p+1][0]), "f"(acc[rt][2*p+1][1]) : "memory");
            }
            if (o1 >= 0) {
                asm volatile("red.global.add.v4.f32 [%0], {%1, %2, %3, %4};"
                    :: "l"(out + (uint32_t)o1 * 64u + col),
                       "f"(acc[rt][2*p][2]), "f"(acc[rt][2*p][3]),
                       "f"(acc[rt][2*p+1][2]), "f"(acc[rt][2*p+1][3]) : "memory");
            }
        }
    }
}

// per-channel sum / sumsq (float4-vectorized) with fused finalize (last block)
__global__ __launch_bounds__(256)
void stats_kernel(const float* __restrict__ x, int N, float* __restrict__ sums,
                  const float* __restrict__ gamma, const float* __restrict__ beta,
                  float invN, float* __restrict__ sb, int cidx)
{
    const int t  = threadIdx.x;
    const int cg = t & 15;        // channel group (4 channels)
    const int rg = t >> 4;        // 16 row lanes per block
    float s0 = 0.f, s1 = 0.f, s2 = 0.f, s3 = 0.f;
    float q0 = 0.f, q1 = 0.f, q2 = 0.f, q3 = 0.f;
    const int stride = gridDim.x * 16;
    for (int r = blockIdx.x * 16 + rg; r < N; r += stride) {
        const float4 v = reinterpret_cast<const float4*>(x + (size_t)r * 64 + cg * 4)[0];
        s0 += v.x; s1 += v.y; s2 += v.z; s3 += v.w;
        q0 += v.x * v.x; q1 += v.y * v.y; q2 += v.z * v.z; q3 += v.w * v.w;
    }
    __shared__ float sh[256 * 8];
    __shared__ int last;
    float* my = sh + t * 8;
    my[0] = s0; my[1] = s1; my[2] = s2; my[3] = s3;
    my[4] = q0; my[5] = q1; my[6] = q2; my[7] = q3;
    __syncthreads();
    if (t < 64) {
        const int cgi = t >> 2;
        const int j   = t & 3;
        float S = 0.f, Q = 0.f;
        #pragma unroll
        for (int r = 0; r < 16; ++r) {
            const float* p = sh + (r * 16 + cgi) * 8 + j;
            S += p[0];
            Q += p[4];
        }
        atomicAdd(&sums[t],      S);
        atomicAdd(&sums[64 + t], Q);
    }
    // last block finalizes scale/shift
    __syncthreads();
    if (t == 0) {
        __threadfence();
        last = (atomicAdd(&g_cnt[cidx], 1u) == gridDim.x - 1) ? 1 : 0;
    }
    __syncthreads();
    if (last && t < 64) {
        const float mean = sums[t] * invN;
        const float var  = fmaxf(sums[64 + t] * invN - mean * mean, 0.f);
        const float s    = gamma[t] * rsqrtf(var + EPSV);
        sb[t]      = s;
        sb[64 + t] = beta[t] - mean * s;
    }
}

__global__ __launch_bounds__(256)
void final_kernel(const float* __restrict__ conv2, const float* __restrict__ sb2,
                  const float* __restrict__ feat, float* __restrict__ out, int n4)
{
    int i = blockIdx.x * blockDim.x + threadIdx.x;
    for (int j = i; j < n4; j += gridDim.x * blockDim.x) {
        const float4 v = reinterpret_cast<const float4*>(conv2)[j];
        const float4 f = reinterpret_cast<const float4*>(feat)[j];
        const int c0 = (j & 15) * 4;
        float4 r;
        r.x = fmaxf(fmaf(v.x, sb2[c0 + 0], sb2[64 + c0 + 0]) + f.x, 0.f);
        r.y = fmaxf(fmaf(v.y, sb2[c0 + 1], sb2[64 + c0 + 1]) + f.y, 0.f);
        r.z = fmaxf(fmaf(v.z, sb2[c0 + 2], sb2[64 + c0 + 2]) + f.z, 0.f);
        r.w = fmaxf(fmaf(v.w, sb2[c0 + 3], sb2[64 + c0 + 3]) + f.w, 0.f);
        reinterpret_cast<float4*>(out)[j] = r;
    }
}

// ================= launcher =================
extern "C" void kernel_launch(void* const* d_in, const int* in_sizes, int n_in,
                              void* d_out, int out_size)
{
    const float* features = (const float*)d_in[0];
    const float* W1       = (const float*)d_in[1];
    const float* gamma1   = (const float*)d_in[2];
    const float* beta1    = (const float*)d_in[3];
    const float* W2       = (const float*)d_in[4];
    const float* gamma2   = (const float*)d_in[5];
    const float* beta2    = (const float*)d_in[6];
    const int*   in_maps  = (const int*)d_in[7];
    const int*   out_maps = (const int*)d_in[8];
    float*       out      = (float*)d_out;

    const int N = in_sizes[0] / CH;
    const int K = in_sizes[1] / (CH * CH);
    const int M = in_sizes[7] / K;

    float* buf1;  cudaGetSymbolAddress((void**)&buf1,  g_buf1);
    float* buf2;  cudaGetSymbolAddress((void**)&buf2,  g_buf2);
    float* stats; cudaGetSymbolAddress((void**)&stats, g_stats);
    float* sb;    cudaGetSymbolAddress((void**)&sb,    g_sb);
    __nv_bfloat16 *fhi, *flo;
    cudaGetSymbolAddress((void**)&fhi, g_fhi);
    cudaGetSymbolAddress((void**)&flo, g_flo);
    uint4 *wf1, *wf2;
    cudaGetSymbolAddress((void**)&wf1, g_Wf1);
    cudaGetSymbolAddress((void**)&wf2, g_Wf2);

    cudaFuncSetAttribute(conv_mma_kernel,
                         cudaFuncAttributeMaxDynamicSharedMemorySize, SMEM_BYTES);

    const int total4 = N * (CH / 4);
    const float invN = 1.0f / (float)N;
    const dim3 convGrid((M + 127) / 128, K);
    const int pfBlocks = (N * 8 + 255) / 256;

    prep_w_kernel<<<dim3(K, 2), 256>>>(W1, W2, K);

    // conv1 (prep also zeroes buf1/buf2)
    prep_feat_kernel<<<pfBlocks, 256>>>(features, nullptr, buf1, buf2, N);
    conv_mma_kernel<<<convGrid, 256, SMEM_BYTES>>>(fhi, flo, wf1,
                                                   in_maps, out_maps, buf1, M);
    stats_kernel<<<512, 256>>>(buf1, N, stats, gamma1, beta1, invN, sb, 0);

    // conv2 (BN1+ReLU fused into split pass)
    prep_feat_kernel<<<pfBlocks, 256>>>(buf1, sb, nullptr, nullptr, N);
    conv_mma_kernel<<<convGrid, 256, SMEM_BYTES>>>(fhi, flo, wf2,
                                                   in_maps, out_maps, buf2, M);
    stats_kernel<<<512, 256>>>(buf2, N, stats + 128, gamma2, beta2, invN,
                               sb + 128, 1);

    final_kernel<<<1024, 256>>>(buf2, sb + 128, features, out, total4);
}